// round 6
// baseline (speedup 1.0000x reference)
#include <cuda_runtime.h>
#include <cuda_fp16.h>
#include <cuda_bf16.h>
#include <mma.h>
#include <math.h>
#include <stdint.h>

using namespace nvcuda;

#define S_LEN 2048
#define D_DIM 4096
#define H_NUM 32
#define HD    128
#define KDIM  4096

// Arch-specific feature gate: tcgen05 only exists under 'a'/'f' targets.
#if defined(__CUDA_ARCH__) && (defined(__CUDA_ARCH_FEAT_SM103_ALL) || defined(__CUDA_ARCH_FEAT_SM100_ALL) || defined(__CUDA_ARCH_SPECIFIC__) || defined(__CUDA_ARCH_FAMILY_SPECIFIC__))
#define USE_TC 1
#else
#define USE_TC 0
#endif

// ---------------- static scratch (allocation-free rule) ----------------
__device__ int8_t g_x8[S_LEN * D_DIM];              // quantized hidden, int8 linear (wmma path)
__device__ int8_t g_w8[4][D_DIM * D_DIM];           // weights int8 linear (wmma path)
__device__ __nv_bfloat16 g_xa[S_LEN * D_DIM];       // quantized hidden, bf16 SW128-tiled (tc path)
__device__ __nv_bfloat16 g_wb[4][D_DIM * D_DIM];    // weights bf16 SW128-tiled (tc path)
__device__ __nv_bfloat16 g_oa[S_LEN * D_DIM];       // attn out bf16 SW128-tiled (tc path)
__device__ int    g_pint[3][S_LEN * D_DIM];         // raw int32 projections (wmma path only)
__device__ int8_t g_q8[H_NUM * S_LEN * HD];         // roped+quantized Q  [H,S,HD]
__device__ int8_t g_k8[H_NUM * S_LEN * HD];         // roped+quantized K  [H,S,HD]
__device__ __half g_vh[H_NUM * HD * S_LEN];         // quantized V TRANSPOSED [H,HD,S]
__device__ int8_t g_oq[S_LEN * D_DIM];              // quantized attention out [S,D] (wmma path)
__device__ float2 g_rope[S_LEN * 64];               // (cos,sin) table
__device__ float  g_t2[4096];                       // exp(-lo*SC)
__device__ float  g_t1[32];                         // exp(-hi*4096*SC)

// ---------------- helpers ----------------
__device__ __forceinline__ void cp_async16(void* smem, const void* gmem) {
    unsigned saddr = (unsigned)__cvta_generic_to_shared(smem);
    asm volatile("cp.async.cg.shared.global [%0], [%1], 16;\n" :: "r"(saddr), "l"(gmem));
}
__device__ __forceinline__ void cp_commit() { asm volatile("cp.async.commit_group;\n"); }
__device__ __forceinline__ int clampi(int v, int lo, int hi) { return max(lo, min(hi, v)); }

// swizzled byte offset inside a [rows x 128B] SW128 tile for (row r, bf16 col c<64)
__device__ __forceinline__ uint32_t sw_off(int r, int c) {
    return (uint32_t)((r * 128 + c * 2) ^ ((r & 7) << 4));
}

// mma.sync wrappers (legal on base arch; used by attention)
__device__ __forceinline__ void imma16832(int* c, const uint32_t* a, uint32_t b0, uint32_t b1) {
    asm volatile("mma.sync.aligned.m16n8k32.row.col.s32.s8.s8.s32 "
        "{%0,%1,%2,%3}, {%4,%5,%6,%7}, {%8,%9}, {%0,%1,%2,%3};"
        : "+r"(c[0]), "+r"(c[1]), "+r"(c[2]), "+r"(c[3])
        : "r"(a[0]), "r"(a[1]), "r"(a[2]), "r"(a[3]), "r"(b0), "r"(b1));
}
__device__ __forceinline__ void hmma16816(float* c, const uint32_t* a, uint32_t b0, uint32_t b1) {
    asm volatile("mma.sync.aligned.m16n8k16.row.col.f32.f16.f16.f32 "
        "{%0,%1,%2,%3}, {%4,%5,%6,%7}, {%8,%9}, {%0,%1,%2,%3};"
        : "+f"(c[0]), "+f"(c[1]), "+f"(c[2]), "+f"(c[3])
        : "r"(a[0]), "r"(a[1]), "r"(a[2]), "r"(a[3]), "r"(b0), "r"(b1));
}
__device__ __forceinline__ void splitpk(float x0, float x1, uint32_t& hi, uint32_t& lo) {
    __half h0 = __float2half_rn(x0), h1 = __float2half_rn(x1);
    __half e0 = __float2half_rn(x0 - __half2float(h0));
    __half e1 = __float2half_rn(x1 - __half2float(h1));
    hi = (uint32_t)__half_as_ushort(h0) | ((uint32_t)__half_as_ushort(h1) << 16);
    lo = (uint32_t)__half_as_ushort(e0) | ((uint32_t)__half_as_ushort(e1) << 16);
}

#if USE_TC
__device__ __forceinline__ uint32_t smem_u32(const void* p) {
    uint32_t a;
    asm("{ .reg .u64 t; cvta.to.shared.u64 t, %1; cvt.u32.u64 %0, t; }" : "=r"(a) : "l"(p));
    return a;
}
#define MBARRIER_INIT(addr, cnt) \
    asm volatile("mbarrier.init.shared.b64 [%0], %1;" :: "r"((uint32_t)(addr)), "r"((uint32_t)(cnt)) : "memory")
#define MBARRIER_EXPECT_TX(addr, bytes) \
    asm volatile("mbarrier.arrive.expect_tx.shared.b64 _, [%0], %1;" :: "r"((uint32_t)(addr)), "r"((uint32_t)(bytes)) : "memory")
#define MBARRIER_WAIT_PARITY(addr, ph) do {                                   \
    uint32_t _m = (uint32_t)(addr); uint32_t _p = (uint32_t)(ph);             \
    asm volatile("{\n\t.reg .pred P1;\n\t"                                    \
        "WL_%=:\n\t"                                                          \
        "mbarrier.try_wait.parity.acquire.cta.shared::cta.b64 P1, [%0], %1, 0x989680;\n\t" \
        "@P1 bra.uni WD_%=;\n\t"                                              \
        "bra.uni WL_%=;\n\t"                                                  \
        "WD_%=:\n\t}"                                                         \
        :: "r"(_m), "r"(_p) : "memory");                                      \
} while (0)
#define TCGEN05_ALLOC(sma, n) \
    asm volatile("tcgen05.alloc.cta_group::1.sync.aligned.shared::cta.b32 [%0], %1;" \
        :: "r"((uint32_t)(sma)), "r"((uint32_t)(n)) : "memory")
#define TCGEN05_DEALLOC(tm, n) \
    asm volatile("tcgen05.dealloc.cta_group::1.sync.aligned.b32 %0, %1;" :: "r"(tm), "r"((uint32_t)(n)))
#define TCGEN05_RELINQ() \
    asm volatile("tcgen05.relinquish_alloc_permit.cta_group::1.sync.aligned;")
#define TCGEN05_COMMIT(mb) \
    asm volatile("tcgen05.commit.cta_group::1.mbarrier::arrive::one.shared::cluster.b64 [%0];" \
        :: "r"((uint32_t)(mb)) : "memory")
#define TCGEN05_FENCE_AFTER() asm volatile("tcgen05.fence::after_thread_sync;" ::: "memory")
#define TCGEN05_WAIT_LD()     asm volatile("tcgen05.wait::ld.sync.aligned;" ::: "memory")
#define TCGEN05_LD_X32(r, tma) \
    asm volatile("tcgen05.ld.sync.aligned.32x32b.x32.b32 " \
        "{%0,%1,%2,%3,%4,%5,%6,%7,%8,%9,%10,%11,%12,%13,%14,%15," \
        "%16,%17,%18,%19,%20,%21,%22,%23,%24,%25,%26,%27,%28,%29,%30,%31}, [%32];" \
        : "=r"((r)[0]), "=r"((r)[1]), "=r"((r)[2]), "=r"((r)[3]),   \
          "=r"((r)[4]), "=r"((r)[5]), "=r"((r)[6]), "=r"((r)[7]),   \
          "=r"((r)[8]), "=r"((r)[9]), "=r"((r)[10]), "=r"((r)[11]), \
          "=r"((r)[12]), "=r"((r)[13]), "=r"((r)[14]), "=r"((r)[15]), \
          "=r"((r)[16]), "=r"((r)[17]), "=r"((r)[18]), "=r"((r)[19]), \
          "=r"((r)[20]), "=r"((r)[21]), "=r"((r)[22]), "=r"((r)[23]), \
          "=r"((r)[24]), "=r"((r)[25]), "=r"((r)[26]), "=r"((r)[27]), \
          "=r"((r)[28]), "=r"((r)[29]), "=r"((r)[30]), "=r"((r)[31]) \
        : "r"(tma))
static constexpr uint64_t SMEM_DESC_BASE_SW128 =
    (uint64_t(2) << 61) | (uint64_t(1) << 46) | (uint64_t(64) << 32) | (uint64_t(1) << 16);
#define MAKE_SMEM_DESC(ba) (SMEM_DESC_BASE_SW128 | ((uint64_t)((ba) >> 4) & 0x3FFF))
__device__ __forceinline__ void bulk_g2s(uint32_t dst, const void* src, uint32_t bytes, uint32_t mbar) {
    asm volatile("cp.async.bulk.shared::cluster.global.mbarrier::complete_tx::bytes [%0], [%1], %2, [%3];"
        :: "r"(dst), "l"(src), "r"(bytes), "r"(mbar) : "memory");
}
__device__ __forceinline__ void mma_f16_cg1(uint32_t d, uint64_t ad, uint64_t bd, uint32_t idesc, bool en) {
    uint32_t e = en ? 1u : 0u;
    asm volatile("{\n\t.reg .pred p;\n\tsetp.ne.u32 p, %5, 0;\n\t"
        "tcgen05.mma.cta_group::1.kind::f16 [%0], %1, %2, %3, {%4, %4, %4, %4}, p;\n\t}"
        :: "r"(d), "l"(ad), "l"(bd), "r"(idesc), "r"(0u), "r"(e) : "memory");
}
#endif  // USE_TC

// ---------------- elementwise kernels ----------------
__global__ void quant_x_kernel(const float* __restrict__ hs) {
    int idx = blockIdx.x * blockDim.x + threadIdx.x;
    if (idx >= S_LEN * D_DIM) return;
    int q = clampi(__float2int_rn(__fdiv_rn(hs[idx], 0.1f)), -128, 127);
#if USE_TC
    int s = idx >> 12, d = idx & (D_DIM - 1);
    int mt = s >> 7, r = s & 127, kt = d >> 6, c = d & 63;
    *(__nv_bfloat16*)((char*)g_xa + (((size_t)(mt * 64 + kt)) << 14) + sw_off(r, c)) =
        __float2bfloat16_rn((float)q);
#else
    g_x8[idx] = (int8_t)q;
#endif
}

__global__ void convert_w_kernel(const float* __restrict__ wq, const float* __restrict__ wk,
                                 const float* __restrict__ wv, const float* __restrict__ wo) {
    int idx = blockIdx.x * blockDim.x + threadIdx.x;
    int z = blockIdx.y;
    if (idx >= D_DIM * D_DIM) return;
    const float* src = (z == 0) ? wq : (z == 1) ? wk : (z == 2) ? wv : wo;
    int w = (int)__float2int_rn(src[idx]);
#if USE_TC
    int o = idx >> 12, k = idx & (D_DIM - 1);
    int nt = o >> 7, r = o & 127, kt = k >> 6, c = k & 63;
    *(__nv_bfloat16*)((char*)g_wb[z] + (((size_t)(nt * 64 + kt)) << 14) + sw_off(r, c)) =
        __float2bfloat16_rn((float)w);
#else
    g_w8[z][idx] = (int8_t)w;
#endif
}

__global__ void rope_table_kernel(const int* __restrict__ pos) {
    int idx = blockIdx.x * blockDim.x + threadIdx.x;
    // exp tables: p = exp(-d*SC) = g_t1[d>>12] * g_t2[d&4095]
    const double SCd = (double)0.1f * (double)0.1f / 11.313708498984760390;
    if (idx < 4096) g_t2[idx] = (float)exp(-SCd * (double)idx);
    if (idx < 32)   g_t1[idx] = (float)exp(-SCd * 4096.0 * (double)idx);
    if (idx >= S_LEN * 64) return;
    int s = idx >> 6, i = idx & 63;
    float e = (float)(2 * i) * (1.0f / 128.0f);
    float powf32 = (float)pow(10000.0, (double)e);
    float invf = 1.0f / powf32;
    float ang = (float)pos[s] * invf;
    double a = (double)ang;
    g_rope[idx] = make_float2((float)cos(a), (float)sin(a));
}

__global__ void ropequant_kernel(const float* __restrict__ sq, const float* __restrict__ sk,
                                 const float* __restrict__ sv) {
#if !USE_TC
    int idx = blockIdx.x * blockDim.x + threadIdx.x;
    if (idx >= S_LEN * D_DIM) return;
    int s = idx >> 12, o = idx & (D_DIM - 1);
    int h = o >> 7, j = o & 127;
    float2 cs = g_rope[(s << 6) + (j & 63)];
    int o2 = (h << 7) + ((j < 64) ? (j + 64) : (j - 64));
    float sign = (j < 64) ? -1.0f : 1.0f;
    int base = s * D_DIM;
    int dsti = (h * S_LEN + s) * HD + j;
    {
        float a = __fmul_rn((float)g_pint[0][base + o],  __fmul_rn(0.1f, sq[o]));
        float b = __fmul_rn((float)g_pint[0][base + o2], __fmul_rn(0.1f, sq[o2])) * sign;
        float r = __fadd_rn(__fmul_rn(a, cs.x), __fmul_rn(b, cs.y));
        g_q8[dsti] = (int8_t)clampi(__float2int_rn(__fdiv_rn(r, 0.1f)), -128, 127);
    }
    {
        float a = __fmul_rn((float)g_pint[1][base + o],  __fmul_rn(0.1f, sk[o]));
        float b = __fmul_rn((float)g_pint[1][base + o2], __fmul_rn(0.1f, sk[o2])) * sign;
        float r = __fadd_rn(__fmul_rn(a, cs.x), __fmul_rn(b, cs.y));
        g_k8[dsti] = (int8_t)clampi(__float2int_rn(__fdiv_rn(r, 0.1f)), -128, 127);
    }
    {
        float a = __fmul_rn((float)g_pint[2][base + o], __fmul_rn(0.1f, sv[o]));
        int q = clampi(__float2int_rn(__fdiv_rn(a, 0.1f)), -128, 127);
        g_vh[((size_t)h * HD + j) * S_LEN + s] = __float2half_rn((float)q);
    }
#endif
}

__global__ void final_kernel(const float* __restrict__ so, float* __restrict__ out) {
#if !USE_TC
    int idx = blockIdx.x * blockDim.x + threadIdx.x;
    if (idx >= S_LEN * D_DIM) return;
    out[idx] = __fmul_rn((float)g_pint[0][idx], __fmul_rn(0.1f, so[idx & (D_DIM - 1)]));
#endif
}

// ---------------- PATH A: legacy wmma int8 GEMM (fallback) ----------------
#define GBM 128
#define GBN 128
#define GBK 64
#define GLD 80

__global__ __launch_bounds__(128) void gemm_s8_kernel(int mode) {
#if !USE_TC
    __shared__ __align__(16) int8_t As[2][GBM * GLD];
    __shared__ __align__(16) int8_t Bs[2][GBN * GLD];
    const int8_t* A; const int8_t* B; int* C;
    if (mode == 0) { A = g_x8; B = g_w8[blockIdx.z]; C = g_pint[blockIdx.z]; }
    else           { A = g_oq; B = g_w8[3];          C = g_pint[0]; }
    const int m0 = blockIdx.y * GBM, n0 = blockIdx.x * GBN;
    int tid = threadIdx.x;
    int w = tid >> 5;
    int wm = w & 1, wn = w >> 1;

    wmma::fragment<wmma::accumulator, 16, 16, 16, int> acc[4][4];
    #pragma unroll
    for (int i = 0; i < 4; i++)
        #pragma unroll
        for (int j = 0; j < 4; j++) wmma::fill_fragment(acc[i][j], 0);

    const int KT = KDIM / GBK;
    #pragma unroll
    for (int c = tid; c < 512; c += 128) {
        int r = c >> 2, off = (c & 3) << 4;
        cp_async16(&As[0][r * GLD + off], A + (size_t)(m0 + r) * KDIM + off);
        cp_async16(&Bs[0][r * GLD + off], B + (size_t)(n0 + r) * KDIM + off);
    }
    cp_commit();

    for (int kt = 0; kt < KT; kt++) {
        int buf = kt & 1;
        asm volatile("cp.async.wait_group 0;\n");
        __syncthreads();
        if (kt + 1 < KT) {
            int k0 = (kt + 1) * GBK;
            #pragma unroll
            for (int c = tid; c < 512; c += 128) {
                int r = c >> 2, off = (c & 3) << 4;
                cp_async16(&As[buf ^ 1][r * GLD + off], A + (size_t)(m0 + r) * KDIM + k0 + off);
                cp_async16(&Bs[buf ^ 1][r * GLD + off], B + (size_t)(n0 + r) * KDIM + k0 + off);
            }
            cp_commit();
        }
        #pragma unroll
        for (int ks = 0; ks < 4; ks++) {
            wmma::fragment<wmma::matrix_a, 16, 16, 16, signed char, wmma::row_major> af[4];
            wmma::fragment<wmma::matrix_b, 16, 16, 16, signed char, wmma::col_major> bf[4];
            #pragma unroll
            for (int i = 0; i < 4; i++)
                wmma::load_matrix_sync(af[i], (const signed char*)&As[buf][(wm * 64 + i * 16) * GLD + ks * 16], GLD);
            #pragma unroll
            for (int j = 0; j < 4; j++)
                wmma::load_matrix_sync(bf[j], (const signed char*)&Bs[buf][(wn * 64 + j * 16) * GLD + ks * 16], GLD);
            #pragma unroll
            for (int i = 0; i < 4; i++)
                #pragma unroll
                for (int j = 0; j < 4; j++)
                    wmma::mma_sync(acc[i][j], af[i], bf[j], acc[i][j]);
        }
        __syncthreads();
    }
    #pragma unroll
    for (int i = 0; i < 4; i++)
        #pragma unroll
        for (int j = 0; j < 4; j++)
            wmma::store_matrix_sync(C + (size_t)(m0 + wm * 64 + i * 16) * D_DIM + (n0 + wn * 64 + j * 16),
                                    acc[i][j], D_DIM, wmma::mem_row_major);
#endif
}

// ---------------- PATH B: tcgen05 bf16 GEMM (M=256, N=256 via 4 quadrants, K-stage 64) ----------------
// mode 0: QKV projections with FUSED rope+requant epilogue (z = 0 Q, 1 K, 2 V)
// mode 1: o-proj with fused output scaling
#define NST 3
#define STG_B 65536                 // A0+A1+B0+B1 (4 x 16KB)
#define T_OFF_TM 0
#define T_OFF_BAR 16
#define T_OFF_DONE 80
#define T_OFF_ST 1024
#define SMEM_TC (T_OFF_ST + NST * STG_B)   // 197632

__global__ __launch_bounds__(128, 1) __cluster_dims__(1, 1, 1)
void gemm_tc_kernel(int mode, const float* __restrict__ sq, const float* __restrict__ sk,
                    const float* __restrict__ sv, const float* __restrict__ so,
                    float* __restrict__ out) {
#if USE_TC
    extern __shared__ __align__(1024) char sm[];
    uint32_t sb = smem_u32(sm);
    int tid = threadIdx.x, wid = tid >> 5, lid = tid & 31;

    const char* A; const char* B;
    int z = blockIdx.z;
    if (mode == 0) { A = (const char*)g_xa; B = (const char*)g_wb[z]; }
    else           { A = (const char*)g_oa; B = (const char*)g_wb[3]; }
    int my = blockIdx.y, nt = blockIdx.x;

    if (wid == 0) { TCGEN05_ALLOC(sb + T_OFF_TM, 512); TCGEN05_RELINQ(); }
    if (tid == 0) {
        #pragma unroll
        for (int s = 0; s < NST; s++) {
            MBARRIER_INIT(sb + T_OFF_BAR + s * 16, 1);
            MBARRIER_INIT(sb + T_OFF_BAR + s * 16 + 8, 1);
        }
        MBARRIER_INIT(sb + T_OFF_DONE, 1);
    }
    __syncthreads();
    uint32_t tmem;
    asm volatile("ld.shared.b32 %0, [%1];" : "=r"(tmem) : "r"(sb + T_OFF_TM));

    const int KT = KDIM / 64;   // 64 stages of K=64

    if (tid == 0) {
        for (int kt = 0; kt < KT; kt++) {
            int st = kt % NST, it = kt / NST;
            uint32_t fullb = sb + T_OFF_BAR + st * 16;
            uint32_t emptyb = fullb + 8;
            if (kt >= NST) MBARRIER_WAIT_PARITY(emptyb, (it - 1) & 1);
            MBARRIER_EXPECT_TX(fullb, STG_B);
            uint32_t dst = sb + T_OFF_ST + st * STG_B;
            bulk_g2s(dst,         A + ((size_t)((2 * my)     * 64 + kt) << 14), 16384, fullb);
            bulk_g2s(dst + 16384, A + ((size_t)((2 * my + 1) * 64 + kt) << 14), 16384, fullb);
            bulk_g2s(dst + 32768, B + ((size_t)((2 * nt)     * 64 + kt) << 14), 16384, fullb);
            bulk_g2s(dst + 49152, B + ((size_t)((2 * nt + 1) * 64 + kt) << 14), 16384, fullb);
        }
    } else if (tid == 32) {
        // idesc kind::f16: dtype F32, a/b BF16, N=128 -> 16<<17, M=128 -> 8<<24 (proven)
        const uint32_t idesc = (1u << 4) | (1u << 7) | (1u << 10) | (16u << 17) | (8u << 24);
        for (int kt = 0; kt < KT; kt++) {
            int st = kt % NST, it = kt / NST;
            uint32_t fullb = sb + T_OFF_BAR + st * 16;
            uint32_t emptyb = fullb + 8;
            MBARRIER_WAIT_PARITY(fullb, it & 1);
            uint32_t base = sb + T_OFF_ST + st * STG_B;
            uint64_t a0 = MAKE_SMEM_DESC(base);
            uint64_t a1 = MAKE_SMEM_DESC(base + 16384);
            uint64_t b0 = MAKE_SMEM_DESC(base + 32768);
            uint64_t b1 = MAKE_SMEM_DESC(base + 49152);
            #pragma unroll
            for (int sub = 0; sub < 4; sub++) {
                bool en = (kt > 0) || (sub > 0);
                mma_f16_cg1(tmem,             a0 + sub * 2, b0 + sub * 2, idesc, en);
                mma_f16_cg1(tmem + 128,       a0 + sub * 2, b1 + sub * 2, idesc, en);
                mma_f16_cg1(tmem + 256,       a1 + sub * 2, b0 + sub * 2, idesc, en);
                mma_f16_cg1(tmem + 256 + 128, a1 + sub * 2, b1 + sub * 2, idesc, en);
            }
            TCGEN05_COMMIT(emptyb);
        }
        TCGEN05_COMMIT(sb + T_OFF_DONE);
    }

    MBARRIER_WAIT_PARITY(sb + T_OFF_DONE, 0);
    TCGEN05_FENCE_AFTER();

    if (mode == 0) {
        // fused rope+requant epilogue
        const float* scl = (z == 0) ? sq : (z == 1) ? sk : sv;
        #pragma unroll
        for (int half = 0; half < 2; half++) {
            int s = my * 256 + half * 128 + wid * 32 + lid;
            #pragma unroll
            for (int hh = 0; hh < 2; hh++) {
                int h = nt * 2 + hh;
                uint32_t tb = tmem + half * 256 + hh * 128;
                if (z < 2) {
                    int8_t* dst = ((z == 0) ? g_q8 : g_k8) + ((size_t)h * S_LEN + s) * HD;
                    #pragma unroll
                    for (int c0 = 0; c0 < 64; c0 += 32) {
                        uint32_t r0[32], r1[32];
                        TCGEN05_LD_X32(r0, tb + c0);
                        TCGEN05_LD_X32(r1, tb + c0 + 64);
                        TCGEN05_WAIT_LD();
                        uint32_t lp[8], hp[8];
                        #pragma unroll
                        for (int g = 0; g < 8; g++) {
                            uint32_t pl = 0, ph = 0;
                            #pragma unroll
                            for (int b = 0; b < 4; b++) {
                                int jj = g * 4 + b;
                                int j = c0 + jj;
                                float2 cs = g_rope[(s << 6) + j];
                                float slo = __fmul_rn(0.1f, scl[h * 128 + j]);
                                float shi = __fmul_rn(0.1f, scl[h * 128 + j + 64]);
                                float alo = __fmul_rn(__uint_as_float(r0[jj]), slo);
                                float ahi = __fmul_rn(__uint_as_float(r1[jj]), shi);
                                float rlo = __fadd_rn(__fmul_rn(alo, cs.x), __fmul_rn(-ahi, cs.y));
                                float rhi = __fadd_rn(__fmul_rn(ahi, cs.x), __fmul_rn(alo, cs.y));
                                int qlo = clampi(__float2int_rn(__fdiv_rn(rlo, 0.1f)), -128, 127);
                                int qhi = clampi(__float2int_rn(__fdiv_rn(rhi, 0.1f)), -128, 127);
                                pl |= ((uint32_t)(uint8_t)(int8_t)qlo) << (b * 8);
                                ph |= ((uint32_t)(uint8_t)(int8_t)qhi) << (b * 8);
                            }
                            lp[g] = pl; hp[g] = ph;
                        }
                        *(uint4*)(dst + c0)      = make_uint4(lp[0], lp[1], lp[2], lp[3]);
                        *(uint4*)(dst + c0 + 16) = make_uint4(lp[4], lp[5], lp[6], lp[7]);
                        *(uint4*)(dst + c0 + 64) = make_uint4(hp[0], hp[1], hp[2], hp[3]);
                        *(uint4*)(dst + c0 + 80) = make_uint4(hp[4], hp[5], hp[6], hp[7]);
                    }
                } else {
                    #pragma unroll
                    for (int c0 = 0; c0 < 128; c0 += 32) {
                        uint32_t r0[32];
                        TCGEN05_LD_X32(r0, tb + c0);
                        TCGEN05_WAIT_LD();
                        #pragma unroll
                        for (int jj = 0; jj < 32; jj++) {
                            int j = c0 + jj;
                            float a = __fmul_rn(__uint_as_float(r0[jj]), __fmul_rn(0.1f, scl[h * 128 + j]));
                            int q = clampi(__float2int_rn(__fdiv_rn(a, 0.1f)), -128, 127);
                            g_vh[((size_t)h * HD + j) * S_LEN + s] = __float2half_rn((float)q);
                        }
                    }
                }
            }
        }
    } else {
        #pragma unroll
        for (int half = 0; half < 2; half++) {
            int mrow = my * 256 + half * 128 + wid * 32 + lid;
            float* Orow = out + (size_t)mrow * D_DIM + nt * 256;
            #pragma unroll
            for (int c0 = 0; c0 < 256; c0 += 32) {
                uint32_t r[32];
                TCGEN05_LD_X32(r, tmem + half * 256 + c0);
                TCGEN05_WAIT_LD();
                #pragma unroll
                for (int j = 0; j < 32; j++) {
                    int col = nt * 256 + c0 + j;
                    Orow[c0 + j] = __fmul_rn(__uint_as_float(r[j]), __fmul_rn(0.1f, so[col]));
                }
            }
        }
    }
    __syncthreads();
    if (wid == 0) TCGEN05_DEALLOC(tmem, 512);
#endif
}

// ---------------- causal flash attention: register FA-2 + integer table softmax ----------------
#define KSTR 144      // K tile row stride (128 s8 + pad)
#define VSTR 272      // V^T tile row stride (128 half + pad)
#define ABUF 53248    // per-buffer bytes: 128*144 + 128*272
#define OFF_T2 (2 * ABUF)
#define OFF_T1 (2 * ABUF + 16384)
#define SMEM_ATT (2 * ABUF + 16384 + 128)

__global__ __launch_bounds__(256, 1) void attn_kernel() {
    extern __shared__ __align__(16) char sm[];
    float* T2s = (float*)(sm + OFF_T2);
    float* T1s = (float*)(sm + OFF_T1);
    int qt = (int)gridDim.x - 1 - (int)blockIdx.x;   // heavy tiles first
    int h = blockIdx.y;
    int tid = threadIdx.x, w = tid >> 5, ln = tid & 31;
    int qr = ln >> 2, qc = ln & 3;

    const int8_t* Kg = g_k8 + (size_t)h * S_LEN * HD;
    const char*   Vg = (const char*)(g_vh + (size_t)h * HD * S_LEN);

    // exp tables into smem
    for (int i = tid; i < 4096; i += 256) T2s[i] = g_t2[i];
    if (tid < 32) T1s[tid] = g_t1[tid];

    // Q a-fragments (resident whole kernel)
    uint32_t qa[4][4];
    {
        const int8_t* Qg = g_q8 + ((size_t)h * S_LEN + qt * 128 + w * 16) * HD;
        #pragma unroll
        for (int ks = 0; ks < 4; ks++) {
            int off = qc * 4 + ks * 32;
            qa[ks][0] = *(const uint32_t*)(Qg + qr * HD + off);
            qa[ks][1] = *(const uint32_t*)(Qg + (qr + 8) * HD + off);
            qa[ks][2] = *(const uint32_t*)(Qg + qr * HD + off + 16);
            qa[ks][3] = *(const uint32_t*)(Qg + (qr + 8) * HD + off + 16);
        }
    }

    float of[16][4];
    #pragma unroll
    for (int i = 0; i < 16; i++) { of[i][0] = of[i][1] = of[i][2] = of[i][3] = 0.0f; }
    int m0i = -(1 << 30), m1i = -(1 << 30);
    float l0 = 0.0f, l1 = 0.0f;

    // prefetch kt = 0 into buffer 0
    {
        char* Ks = sm; char* Vt = sm + 128 * KSTR;
        for (int c = tid; c < 1024; c += 256)
            cp_async16(Ks + (c >> 3) * KSTR + (c & 7) * 16, Kg + (size_t)(c >> 3) * HD + (c & 7) * 16);
        for (int c = tid; c < 2048; c += 256)
            cp_async16(Vt + (c >> 4) * VSTR + (c & 15) * 16, Vg + ((size_t)(c >> 4) * S_LEN) * 2 + (c & 15) * 16);
        cp_commit();
    }

    for (int kt = 0; kt <= qt; kt++) {
        int buf = kt & 1;
        char* Ks = sm + buf * ABUF;
        char* Vt = Ks + 128 * KSTR;
        if (kt < qt) {
            char* Ks2 = sm + (buf ^ 1) * ABUF;
            char* Vt2 = Ks2 + 128 * KSTR;
            const int8_t* Kt = Kg + (size_t)(kt + 1) * 128 * HD;
            const char*   Vs = Vg + (size_t)(kt + 1) * 128 * 2;
            for (int c = tid; c < 1024; c += 256)
                cp_async16(Ks2 + (c >> 3) * KSTR + (c & 7) * 16, Kt + (size_t)(c >> 3) * HD + (c & 7) * 16);
            for (int c = tid; c < 2048; c += 256)
                cp_async16(Vt2 + (c >> 4) * VSTR + (c & 15) * 16, Vs + ((size_t)(c >> 4) * S_LEN) * 2 + (c & 15) * 16);
            cp_commit();
            asm volatile("cp.async.wait_group 1;\n");
        } else {
            asm volatile("cp.async.wait_group 0;\n");
        }
        __syncthreads();

        // ---- S = Q K^T (exact int), per-nf to limit register pressure ----
        int ds[16][4];
        #pragma unroll
        for (int nf = 0; nf < 16; nf++) {
            int c4[4] = {0, 0, 0, 0};
            #pragma unroll
            for (int ks = 0; ks < 4; ks++) {
                const char* bp = Ks + (nf * 8 + qr) * KSTR + qc * 4 + ks * 32;
                imma16832(c4, qa[ks], *(const uint32_t*)bp, *(const uint32_t*)(bp + 16));
            }
            ds[nf][0] = c4[0]; ds[nf][1] = c4[1]; ds[nf][2] = c4[2]; ds[nf][3] = c4[3];
        }

        // causal mask on diagonal tile (score -> very negative int => p = 0)
        if (kt == qt) {
            #pragma unroll
            for (int nf = 0; nf < 16; nf++) {
                #pragma unroll
                for (int c = 0; c < 4; c++) {
                    int col = nf * 8 + qc * 2 + (c & 1);
                    int rowl = w * 16 + qr + ((c >> 1) << 3);
                    if (col > rowl) ds[nf][c] = -(1 << 29);
                }
            }
        }

        // ---- online softmax via integer table exp ----
        int tmx0 = -(1 << 30), tmx1 = -(1 << 30);
        #pragma unroll
        for (int nf = 0; nf < 16; nf++) {
            tmx0 = max(tmx0, max(ds[nf][0], ds[nf][1]));
            tmx1 = max(tmx1, max(ds[nf][2], ds[nf][3]));
        }
        tmx0 = max(tmx0, __shfl_xor_sync(0xffffffffu, tmx0, 1));
        tmx0 = max(tmx0, __shfl_xor_sync(0xffffffffu, tmx0, 2));
        tmx1 = max(tmx1, __shfl_xor_sync(0xffffffffu, tmx1, 1));
        tmx1 = max(tmx1, __shfl_xor_sync(0xffffffffu, tmx1, 2));
        int mn0 = max(m0i, tmx0), mn1 = max(m1i, tmx1);
        int da0 = mn0 - m0i, da1 = mn1 - m1i;
        float al0 = T1s[min(da0 >> 12, 31)] * T2s[da0 & 4095];
        float al1 = T1s[min(da1 >> 12, 31)] * T2s[da1 & 4095];
        m0i = mn0; m1i = mn1;
        float ps0 = 0.0f, ps1 = 0.0f;
        #pragma unroll
        for (int nf = 0; nf < 16; nf++) {
            int d0 = mn0 - ds[nf][0], d1 = mn0 - ds[nf][1];
            int d2 = mn1 - ds[nf][2], d3 = mn1 - ds[nf][3];
            float p0 = T1s[min(d0 >> 12, 31)] * T2s[d0 & 4095];
            float p1 = T1s[min(d1 >> 12, 31)] * T2s[d1 & 4095];
            float p2 = T1s[min(d2 >> 12, 31)] * T2s[d2 & 4095];
            float p3 = T1s[min(d3 >> 12, 31)] * T2s[d3 & 4095];
            ds[nf][0] = __float_as_int(p0); ds[nf][1] = __float_as_int(p1);
            ds[nf][2] = __float_as_int(p2); ds[nf][3] = __float_as_int(p3);
            ps0 += p0 + p1; ps1 += p2 + p3;
        }
        ps0 += __shfl_xor_sync(0xffffffffu, ps0, 1);
        ps0 += __shfl_xor_sync(0xffffffffu, ps0, 2);
        ps1 += __shfl_xor_sync(0xffffffffu, ps1, 1);
        ps1 += __shfl_xor_sync(0xffffffffu, ps1, 2);
        l0 = l0 * al0 + ps0;
        l1 = l1 * al1 + ps1;
        #pragma unroll
        for (int nf = 0; nf < 16; nf++) {
            of[nf][0] *= al0; of[nf][1] *= al0; of[nf][2] *= al1; of[nf][3] *= al1;
        }

        // ---- O += (Phi + Plo) * V (split fp16) ----
        #pragma unroll
        for (int ks = 0; ks < 8; ks++) {
            uint32_t ah[4], alr[4];
            splitpk(__int_as_float(ds[2 * ks][0]),     __int_as_float(ds[2 * ks][1]),     ah[0], alr[0]);
            splitpk(__int_as_float(ds[2 * ks][2]),     __int_as_float(ds[2 * ks][3]),     ah[1], alr[1]);
            splitpk(__int_as_float(ds[2 * ks + 1][0]), __int_as_float(ds[2 * ks + 1][1]), ah[2], alr[2]);
            splitpk(__int_as_float(ds[2 * ks + 1][2]), __int_as_float(ds[2 * ks + 1][3]), ah[3], alr[3]);
            #pragma unroll
            for (int nf = 0; nf < 16; nf++) {
                const char* vp = Vt + (nf * 8 + qr) * VSTR + qc * 4 + ks * 32;
                uint32_t b0 = *(const uint32_t*)vp;
                uint32_t b1 = *(const uint32_t*)(vp + 16);
                hmma16816(of[nf], ah,  b0, b1);
                hmma16816(of[nf], alr, b0, b1);
            }
        }
        __syncthreads();
    }

    // ---- epilogue: quantize round(x/0.1) clamp -127..127, write for o-proj ----
    {
        int s0 = qt * 128 + w * 16 + qr;
        int s1 = s0 + 8;
        #pragma unroll
        for (int nf = 0; nf < 16; nf++) {
            int colb = nf * 8 + qc * 2;
            float x00 = __fmul_rn(__fdiv_rn(of[nf][0], l0), 0.1f);
            float x01 = __fmul_rn(__fdiv_rn(of[nf][1], l0), 0.1f);
            float x10 = __fmul_rn(__fdiv_rn(of[nf][2], l1), 0.1f);
            float x11 = __fmul_rn(__fdiv_rn(of[nf][3], l1), 0.1f);
            int q00 = clampi(__float2int_rn(__fdiv_rn(x00, 0.1f)), -127, 127);
            int q01 = clampi(__float2int_rn(__fdiv_rn(x01, 0.1f)), -127, 127);
            int q10 = clampi(__float2int_rn(__fdiv_rn(x10, 0.1f)), -127, 127);
            int q11 = clampi(__float2int_rn(__fdiv_rn(x11, 0.1f)), -127, 127);
#if USE_TC
            int kcol = h * HD + colb;
            int ktile = kcol >> 6, cc = kcol & 63;
            uint32_t p0 = (uint32_t)__bfloat16_as_ushort(__float2bfloat16_rn((float)q00)) |
                          ((uint32_t)__bfloat16_as_ushort(__float2bfloat16_rn((float)q01)) << 16);
            uint32_t p1 = (uint32_t)__bfloat16_as_ushort(__float2bfloat16_rn((float)q10)) |
                          ((uint32_t)__bfloat16_as_ushort(__float2bfloat16_rn((float)q11)) << 16);
            *(uint32_t*)((char*)g_oa + (((size_t)((s0 >> 7) * 64 + ktile)) << 14) + sw_off(s0 & 127, cc)) = p0;
            *(uint32_t*)((char*)g_oa + (((size_t)((s1 >> 7) * 64 + ktile)) << 14) + sw_off(s1 & 127, cc)) = p1;
#else
            uint16_t u0 = (uint16_t)((uint8_t)(int8_t)q00 | ((uint16_t)(uint8_t)(int8_t)q01 << 8));
            uint16_t u1 = (uint16_t)((uint8_t)(int8_t)q10 | ((uint16_t)(uint8_t)(int8_t)q11 << 8));
            *(uint16_t*)(g_oq + (size_t)s0 * D_DIM + h * HD + colb) = u0;
            *(uint16_t*)(g_oq + (size_t)s1 * D_DIM + h * HD + colb) = u1;
#endif
        }
    }
}

// ---------------- launch ----------------
extern "C" void kernel_launch(void* const* d_in, const int* in_sizes, int n_in,
                              void* d_out, int out_size) {
    const float* hs = (const float*)d_in[0];
    const float* wq = (const float*)d_in[1];
    const float* wk = (const float*)d_in[2];
    const float* wv = (const float*)d_in[3];
    const float* wo = (const float*)d_in[4];
    const float* sq = (const float*)d_in[5];
    const float* sk = (const float*)d_in[6];
    const float* sv = (const float*)d_in[7];
    const float* so = (const float*)d_in[8];
    const int*   pos = (const int*)d_in[10];
    float* out = (float*)d_out;

    cudaFuncSetAttribute(attn_kernel, cudaFuncAttributeMaxDynamicSharedMemorySize, SMEM_ATT);
    cudaFuncSetAttribute(gemm_tc_kernel, cudaFuncAttributeMaxDynamicSharedMemorySize, SMEM_TC);

    quant_x_kernel<<<(S_LEN * D_DIM + 255) / 256, 256>>>(hs);
    convert_w_kernel<<<dim3((D_DIM * D_DIM + 255) / 256, 4), 256>>>(wq, wk, wv, wo);
    rope_table_kernel<<<(S_LEN * 64 + 255) / 256, 256>>>(pos);

    // QKV projections (tc path: fused rope/requant epilogue)
    gemm_s8_kernel<<<dim3(D_DIM / GBN, S_LEN / GBM, 3), 128>>>(0);
    gemm_tc_kernel<<<dim3(D_DIM / 256, S_LEN / 256, 3), 128, SMEM_TC>>>(0, sq, sk, sv, so, out);

    ropequant_kernel<<<(S_LEN * D_DIM + 255) / 256, 256>>>(sq, sk, sv);   // fallback path only

    attn_kernel<<<dim3(S_LEN / 128, H_NUM), 256, SMEM_ATT>>>();

    // o-proj (tc path fuses the output scaling; wmma path uses final_kernel)
    gemm_s8_kernel<<<dim3(D_DIM / GBN, S_LEN / GBM, 1), 128>>>(1);
    gemm_tc_kernel<<<dim3(D_DIM / 256, S_LEN / 256, 1), 128, SMEM_TC>>>(1, sq, sk, sv, so, out);

    final_kernel<<<(S_LEN * D_DIM + 255) / 256, 256>>>(so, out);
}

// round 7
// speedup vs baseline: 1.1565x; 1.1565x over previous
#include <cuda_runtime.h>
#include <cuda_fp16.h>
#include <cuda_bf16.h>
#include <mma.h>
#include <math.h>
#include <stdint.h>

using namespace nvcuda;

#define S_LEN 2048
#define D_DIM 4096
#define H_NUM 32
#define HD    128
#define KDIM  4096

// Arch-specific feature gate: tcgen05 only exists under 'a'/'f' targets.
#if defined(__CUDA_ARCH__) && (defined(__CUDA_ARCH_FEAT_SM103_ALL) || defined(__CUDA_ARCH_FEAT_SM100_ALL) || defined(__CUDA_ARCH_SPECIFIC__) || defined(__CUDA_ARCH_FAMILY_SPECIFIC__))
#define USE_TC 1
#else
#define USE_TC 0
#endif

// ---------------- static scratch (allocation-free rule) ----------------
__device__ int8_t g_x8[S_LEN * D_DIM];              // quantized hidden, int8 linear (wmma path)
__device__ int8_t g_w8[4][D_DIM * D_DIM];           // weights int8 linear (wmma path)
__device__ __nv_bfloat16 g_xa[S_LEN * D_DIM];       // quantized hidden, bf16 SW128-tiled (tc path)
__device__ __nv_bfloat16 g_wb[4][D_DIM * D_DIM];    // weights bf16 SW128-tiled (tc path)
__device__ __nv_bfloat16 g_oa[S_LEN * D_DIM];       // attn out bf16 SW128-tiled (tc path)
__device__ int    g_pint[3][S_LEN * D_DIM];         // raw int32 projections; [0] reused for o-proj (wmma path)
__device__ int8_t g_q8[H_NUM * S_LEN * HD];         // roped+quantized Q  [H,S,HD]
__device__ int8_t g_k8[H_NUM * S_LEN * HD];         // roped+quantized K  [H,S,HD]
__device__ __half g_vh[H_NUM * HD * S_LEN];         // quantized V TRANSPOSED [H,HD,S]
__device__ int8_t g_oq[S_LEN * D_DIM];              // quantized attention out [S,D] (wmma path)
__device__ float2 g_rope[S_LEN * 64];               // (cos,sin) table
__device__ float  g_t2[4096];                       // exp(-lo*SC)
__device__ float  g_t1[32];                         // exp(-hi*4096*SC)

// ---------------- helpers ----------------
__device__ __forceinline__ void cp_async16(void* smem, const void* gmem) {
    unsigned saddr = (unsigned)__cvta_generic_to_shared(smem);
    asm volatile("cp.async.cg.shared.global [%0], [%1], 16;\n" :: "r"(saddr), "l"(gmem));
}
__device__ __forceinline__ void cp_commit() { asm volatile("cp.async.commit_group;\n"); }
__device__ __forceinline__ int clampi(int v, int lo, int hi) { return max(lo, min(hi, v)); }

// swizzled byte offset inside a [rows x 128B] SW128 tile for (row r, bf16 col c<64)
__device__ __forceinline__ uint32_t sw_off(int r, int c) {
    return (uint32_t)((r * 128 + c * 2) ^ ((r & 7) << 4));
}

// mma.sync wrappers (legal on base arch; used by attention)
__device__ __forceinline__ void imma16832(int* c, const uint32_t* a, uint32_t b0, uint32_t b1) {
    asm volatile("mma.sync.aligned.m16n8k32.row.col.s32.s8.s8.s32 "
        "{%0,%1,%2,%3}, {%4,%5,%6,%7}, {%8,%9}, {%0,%1,%2,%3};"
        : "+r"(c[0]), "+r"(c[1]), "+r"(c[2]), "+r"(c[3])
        : "r"(a[0]), "r"(a[1]), "r"(a[2]), "r"(a[3]), "r"(b0), "r"(b1));
}
__device__ __forceinline__ void hmma16816(float* c, const uint32_t* a, uint32_t b0, uint32_t b1) {
    asm volatile("mma.sync.aligned.m16n8k16.row.col.f32.f16.f16.f32 "
        "{%0,%1,%2,%3}, {%4,%5,%6,%7}, {%8,%9}, {%0,%1,%2,%3};"
        : "+f"(c[0]), "+f"(c[1]), "+f"(c[2]), "+f"(c[3])
        : "r"(a[0]), "r"(a[1]), "r"(a[2]), "r"(a[3]), "r"(b0), "r"(b1));
}
__device__ __forceinline__ void splitpk(float x0, float x1, uint32_t& hi, uint32_t& lo) {
    __half h0 = __float2half_rn(x0), h1 = __float2half_rn(x1);
    __half e0 = __float2half_rn(x0 - __half2float(h0));
    __half e1 = __float2half_rn(x1 - __half2float(h1));
    hi = (uint32_t)__half_as_ushort(h0) | ((uint32_t)__half_as_ushort(h1) << 16);
    lo = (uint32_t)__half_as_ushort(e0) | ((uint32_t)__half_as_ushort(e1) << 16);
}

#if USE_TC
__device__ __forceinline__ uint32_t smem_u32(const void* p) {
    uint32_t a;
    asm("{ .reg .u64 t; cvta.to.shared.u64 t, %1; cvt.u32.u64 %0, t; }" : "=r"(a) : "l"(p));
    return a;
}
#define MBARRIER_INIT(addr, cnt) \
    asm volatile("mbarrier.init.shared.b64 [%0], %1;" :: "r"((uint32_t)(addr)), "r"((uint32_t)(cnt)) : "memory")
#define MBARRIER_EXPECT_TX(addr, bytes) \
    asm volatile("mbarrier.arrive.expect_tx.shared.b64 _, [%0], %1;" :: "r"((uint32_t)(addr)), "r"((uint32_t)(bytes)) : "memory")
#define MBARRIER_WAIT_PARITY(addr, ph) do {                                   \
    uint32_t _m = (uint32_t)(addr); uint32_t _p = (uint32_t)(ph);             \
    asm volatile("{\n\t.reg .pred P1;\n\t"                                    \
        "WL_%=:\n\t"                                                          \
        "mbarrier.try_wait.parity.acquire.cta.shared::cta.b64 P1, [%0], %1, 0x989680;\n\t" \
        "@P1 bra.uni WD_%=;\n\t"                                              \
        "bra.uni WL_%=;\n\t"                                                  \
        "WD_%=:\n\t}"                                                         \
        :: "r"(_m), "r"(_p) : "memory");                                      \
} while (0)
#define TCGEN05_ALLOC(sma, n) \
    asm volatile("tcgen05.alloc.cta_group::1.sync.aligned.shared::cta.b32 [%0], %1;" \
        :: "r"((uint32_t)(sma)), "r"((uint32_t)(n)) : "memory")
#define TCGEN05_DEALLOC(tm, n) \
    asm volatile("tcgen05.dealloc.cta_group::1.sync.aligned.b32 %0, %1;" :: "r"(tm), "r"((uint32_t)(n)))
#define TCGEN05_RELINQ() \
    asm volatile("tcgen05.relinquish_alloc_permit.cta_group::1.sync.aligned;")
#define TCGEN05_COMMIT(mb) \
    asm volatile("tcgen05.commit.cta_group::1.mbarrier::arrive::one.shared::cluster.b64 [%0];" \
        :: "r"((uint32_t)(mb)) : "memory")
#define TCGEN05_FENCE_AFTER() asm volatile("tcgen05.fence::after_thread_sync;" ::: "memory")
#define TCGEN05_WAIT_LD()     asm volatile("tcgen05.wait::ld.sync.aligned;" ::: "memory")
#define TCGEN05_LD_X32(r, tma) \
    asm volatile("tcgen05.ld.sync.aligned.32x32b.x32.b32 " \
        "{%0,%1,%2,%3,%4,%5,%6,%7,%8,%9,%10,%11,%12,%13,%14,%15," \
        "%16,%17,%18,%19,%20,%21,%22,%23,%24,%25,%26,%27,%28,%29,%30,%31}, [%32];" \
        : "=r"((r)[0]), "=r"((r)[1]), "=r"((r)[2]), "=r"((r)[3]),   \
          "=r"((r)[4]), "=r"((r)[5]), "=r"((r)[6]), "=r"((r)[7]),   \
          "=r"((r)[8]), "=r"((r)[9]), "=r"((r)[10]), "=r"((r)[11]), \
          "=r"((r)[12]), "=r"((r)[13]), "=r"((r)[14]), "=r"((r)[15]), \
          "=r"((r)[16]), "=r"((r)[17]), "=r"((r)[18]), "=r"((r)[19]), \
          "=r"((r)[20]), "=r"((r)[21]), "=r"((r)[22]), "=r"((r)[23]), \
          "=r"((r)[24]), "=r"((r)[25]), "=r"((r)[26]), "=r"((r)[27]), \
          "=r"((r)[28]), "=r"((r)[29]), "=r"((r)[30]), "=r"((r)[31]) \
        : "r"(tma))
static constexpr uint64_t SMEM_DESC_BASE_SW128 =
    (uint64_t(2) << 61) | (uint64_t(1) << 46) | (uint64_t(64) << 32) | (uint64_t(1) << 16);
#define MAKE_SMEM_DESC(ba) (SMEM_DESC_BASE_SW128 | ((uint64_t)((ba) >> 4) & 0x3FFF))
__device__ __forceinline__ void bulk_g2s(uint32_t dst, const void* src, uint32_t bytes, uint32_t mbar) {
    asm volatile("cp.async.bulk.shared::cluster.global.mbarrier::complete_tx::bytes [%0], [%1], %2, [%3];"
        :: "r"(dst), "l"(src), "r"(bytes), "r"(mbar) : "memory");
}
__device__ __forceinline__ void mma_f16_cg1(uint32_t d, uint64_t ad, uint64_t bd, uint32_t idesc, bool en) {
    uint32_t e = en ? 1u : 0u;
    asm volatile("{\n\t.reg .pred p;\n\tsetp.ne.u32 p, %5, 0;\n\t"
        "tcgen05.mma.cta_group::1.kind::f16 [%0], %1, %2, %3, {%4, %4, %4, %4}, p;\n\t}"
        :: "r"(d), "l"(ad), "l"(bd), "r"(idesc), "r"(0u), "r"(e) : "memory");
}
#endif  // USE_TC

// ---------------- elementwise kernels ----------------
__global__ void quant_x_kernel(const float* __restrict__ hs) {
    int idx = blockIdx.x * blockDim.x + threadIdx.x;
    if (idx >= S_LEN * D_DIM) return;
    int q = clampi(__float2int_rn(__fdiv_rn(hs[idx], 0.1f)), -128, 127);
#if USE_TC
    int s = idx >> 12, d = idx & (D_DIM - 1);
    int mt = s >> 7, r = s & 127, kt = d >> 6, c = d & 63;
    *(__nv_bfloat16*)((char*)g_xa + (((size_t)(mt * 64 + kt)) << 14) + sw_off(r, c)) =
        __float2bfloat16_rn((float)q);
#else
    g_x8[idx] = (int8_t)q;
#endif
}

__global__ void convert_w_kernel(const float* __restrict__ wq, const float* __restrict__ wk,
                                 const float* __restrict__ wv, const float* __restrict__ wo) {
    int idx = blockIdx.x * blockDim.x + threadIdx.x;
    int z = blockIdx.y;
    if (idx >= D_DIM * D_DIM) return;
    const float* src = (z == 0) ? wq : (z == 1) ? wk : (z == 2) ? wv : wo;
    int w = (int)__float2int_rn(src[idx]);
#if USE_TC
    int o = idx >> 12, k = idx & (D_DIM - 1);
    int nt = o >> 7, r = o & 127, kt = k >> 6, c = k & 63;
    *(__nv_bfloat16*)((char*)g_wb[z] + (((size_t)(nt * 64 + kt)) << 14) + sw_off(r, c)) =
        __float2bfloat16_rn((float)w);
#else
    g_w8[z][idx] = (int8_t)w;
#endif
}

__global__ void rope_table_kernel(const int* __restrict__ pos) {
    int idx = blockIdx.x * blockDim.x + threadIdx.x;
    // exp tables: p = exp(-d*SC) = g_t1[d>>12] * g_t2[d&4095]
    const double SCd = (double)0.1f * (double)0.1f / 11.313708498984760390;
    if (idx < 4096) g_t2[idx] = (float)exp(-SCd * (double)idx);
    if (idx < 32)   g_t1[idx] = (float)exp(-SCd * 4096.0 * (double)idx);
    if (idx >= S_LEN * 64) return;
    int s = idx >> 6, i = idx & 63;
    float e = (float)(2 * i) * (1.0f / 128.0f);
    float powf32 = (float)pow(10000.0, (double)e);
    float invf = 1.0f / powf32;
    float ang = (float)pos[s] * invf;
    double a = (double)ang;
    g_rope[idx] = make_float2((float)cos(a), (float)sin(a));
}

__global__ void ropequant_kernel(const float* __restrict__ sq, const float* __restrict__ sk,
                                 const float* __restrict__ sv) {
    int idx = blockIdx.x * blockDim.x + threadIdx.x;
    if (idx >= S_LEN * D_DIM) return;
    int s = idx >> 12, o = idx & (D_DIM - 1);
    int h = o >> 7, j = o & 127;
    float2 cs = g_rope[(s << 6) + (j & 63)];
    int o2 = (h << 7) + ((j < 64) ? (j + 64) : (j - 64));
    float sign = (j < 64) ? -1.0f : 1.0f;
    int base = s * D_DIM;
    int dsti = (h * S_LEN + s) * HD + j;
    {
        float a = __fmul_rn((float)g_pint[0][base + o],  __fmul_rn(0.1f, sq[o]));
        float b = __fmul_rn((float)g_pint[0][base + o2], __fmul_rn(0.1f, sq[o2])) * sign;
        float r = __fadd_rn(__fmul_rn(a, cs.x), __fmul_rn(b, cs.y));
        g_q8[dsti] = (int8_t)clampi(__float2int_rn(__fdiv_rn(r, 0.1f)), -128, 127);
    }
    {
        float a = __fmul_rn((float)g_pint[1][base + o],  __fmul_rn(0.1f, sk[o]));
        float b = __fmul_rn((float)g_pint[1][base + o2], __fmul_rn(0.1f, sk[o2])) * sign;
        float r = __fadd_rn(__fmul_rn(a, cs.x), __fmul_rn(b, cs.y));
        g_k8[dsti] = (int8_t)clampi(__float2int_rn(__fdiv_rn(r, 0.1f)), -128, 127);
    }
    {
        float a = __fmul_rn((float)g_pint[2][base + o], __fmul_rn(0.1f, sv[o]));
        int q = clampi(__float2int_rn(__fdiv_rn(a, 0.1f)), -128, 127);
        // V stored TRANSPOSED per head: [h][d][s]
        g_vh[((size_t)h * HD + j) * S_LEN + s] = __float2half_rn((float)q);
    }
}

__global__ void final_kernel(const float* __restrict__ so, float* __restrict__ out) {
#if !USE_TC
    int idx = blockIdx.x * blockDim.x + threadIdx.x;
    if (idx >= S_LEN * D_DIM) return;
    out[idx] = __fmul_rn((float)g_pint[0][idx], __fmul_rn(0.1f, so[idx & (D_DIM - 1)]));
#endif
}

// ---------------- PATH A: legacy wmma int8 GEMM (fallback) ----------------
#define GBM 128
#define GBN 128
#define GBK 64
#define GLD 80

__global__ __launch_bounds__(128) void gemm_s8_kernel(int mode) {
#if !USE_TC
    __shared__ __align__(16) int8_t As[2][GBM * GLD];
    __shared__ __align__(16) int8_t Bs[2][GBN * GLD];
    const int8_t* A; const int8_t* B; int* C;
    if (mode == 0) { A = g_x8; B = g_w8[blockIdx.z]; C = g_pint[blockIdx.z]; }
    else           { A = g_oq; B = g_w8[3];          C = g_pint[0]; }
    const int m0 = blockIdx.y * GBM, n0 = blockIdx.x * GBN;
    int tid = threadIdx.x;
    int w = tid >> 5;
    int wm = w & 1, wn = w >> 1;

    wmma::fragment<wmma::accumulator, 16, 16, 16, int> acc[4][4];
    #pragma unroll
    for (int i = 0; i < 4; i++)
        #pragma unroll
        for (int j = 0; j < 4; j++) wmma::fill_fragment(acc[i][j], 0);

    const int KT = KDIM / GBK;
    #pragma unroll
    for (int c = tid; c < 512; c += 128) {
        int r = c >> 2, off = (c & 3) << 4;
        cp_async16(&As[0][r * GLD + off], A + (size_t)(m0 + r) * KDIM + off);
        cp_async16(&Bs[0][r * GLD + off], B + (size_t)(n0 + r) * KDIM + off);
    }
    cp_commit();

    for (int kt = 0; kt < KT; kt++) {
        int buf = kt & 1;
        asm volatile("cp.async.wait_group 0;\n");
        __syncthreads();
        if (kt + 1 < KT) {
            int k0 = (kt + 1) * GBK;
            #pragma unroll
            for (int c = tid; c < 512; c += 128) {
                int r = c >> 2, off = (c & 3) << 4;
                cp_async16(&As[buf ^ 1][r * GLD + off], A + (size_t)(m0 + r) * KDIM + k0 + off);
                cp_async16(&Bs[buf ^ 1][r * GLD + off], B + (size_t)(n0 + r) * KDIM + k0 + off);
            }
            cp_commit();
        }
        #pragma unroll
        for (int ks = 0; ks < 4; ks++) {
            wmma::fragment<wmma::matrix_a, 16, 16, 16, signed char, wmma::row_major> af[4];
            wmma::fragment<wmma::matrix_b, 16, 16, 16, signed char, wmma::col_major> bf[4];
            #pragma unroll
            for (int i = 0; i < 4; i++)
                wmma::load_matrix_sync(af[i], (const signed char*)&As[buf][(wm * 64 + i * 16) * GLD + ks * 16], GLD);
            #pragma unroll
            for (int j = 0; j < 4; j++)
                wmma::load_matrix_sync(bf[j], (const signed char*)&Bs[buf][(wn * 64 + j * 16) * GLD + ks * 16], GLD);
            #pragma unroll
            for (int i = 0; i < 4; i++)
                #pragma unroll
                for (int j = 0; j < 4; j++)
                    wmma::mma_sync(acc[i][j], af[i], bf[j], acc[i][j]);
        }
        __syncthreads();
    }
    #pragma unroll
    for (int i = 0; i < 4; i++)
        #pragma unroll
        for (int j = 0; j < 4; j++)
            wmma::store_matrix_sync(C + (size_t)(m0 + wm * 64 + i * 16) * D_DIM + (n0 + wn * 64 + j * 16),
                                    acc[i][j], D_DIM, wmma::mem_row_major);
#endif
}

// ---------------- PATH B: tcgen05 bf16 GEMM (M=256 via 2x M128, N=128, K-stage 64) ----------------
#define NST 4
#define STG_B 49152                 // A0 16KB + A1 16KB + B 16KB
#define T_OFF_TM 0
#define T_OFF_BAR 16
#define T_OFF_DONE 80
#define T_OFF_ST 1024
#define SMEM_TC (T_OFF_ST + NST * STG_B)   // 197632

__global__ __launch_bounds__(128, 1) __cluster_dims__(1, 1, 1)
void gemm_tc_kernel(int mode, const float* __restrict__ so, float* __restrict__ out) {
#if USE_TC
    extern __shared__ __align__(1024) char sm[];
    uint32_t sb = smem_u32(sm);
    int tid = threadIdx.x, wid = tid >> 5, lid = tid & 31;

    const char* A; const char* B; int* C;
    if (mode == 0) { A = (const char*)g_xa; B = (const char*)g_wb[blockIdx.z]; C = g_pint[blockIdx.z]; }
    else           { A = (const char*)g_oa; B = (const char*)g_wb[3];          C = g_pint[0]; }
    int my = blockIdx.y, nt = blockIdx.x;

    if (wid == 0) { TCGEN05_ALLOC(sb + T_OFF_TM, 256); TCGEN05_RELINQ(); }
    if (tid == 0) {
        #pragma unroll
        for (int s = 0; s < NST; s++) {
            MBARRIER_INIT(sb + T_OFF_BAR + s * 16, 1);
            MBARRIER_INIT(sb + T_OFF_BAR + s * 16 + 8, 1);
        }
        MBARRIER_INIT(sb + T_OFF_DONE, 1);
    }
    __syncthreads();
    uint32_t tmem;
    asm volatile("ld.shared.b32 %0, [%1];" : "=r"(tmem) : "r"(sb + T_OFF_TM));

    const int KT = KDIM / 64;   // 64 stages of K=64

    if (tid == 0) {
        for (int kt = 0; kt < KT; kt++) {
            int st = kt & (NST - 1);
            uint32_t fullb = sb + T_OFF_BAR + st * 16;
            uint32_t emptyb = fullb + 8;
            if (kt >= NST) MBARRIER_WAIT_PARITY(emptyb, ((kt >> 2) - 1) & 1);
            MBARRIER_EXPECT_TX(fullb, STG_B);
            uint32_t dst = sb + T_OFF_ST + st * STG_B;
            bulk_g2s(dst,         A + ((size_t)((2 * my)     * 64 + kt) << 14), 16384, fullb);
            bulk_g2s(dst + 16384, A + ((size_t)((2 * my + 1) * 64 + kt) << 14), 16384, fullb);
            bulk_g2s(dst + 32768, B + ((size_t)(nt * 64 + kt) << 14),           16384, fullb);
        }
    } else if (tid == 32) {
        // idesc kind::f16: dtype F32, a/b BF16, N=128 -> 16<<17, M=128 -> 8<<24 (proven)
        const uint32_t idesc = (1u << 4) | (1u << 7) | (1u << 10) | (16u << 17) | (8u << 24);
        for (int kt = 0; kt < KT; kt++) {
            int st = kt & (NST - 1);
            uint32_t fullb = sb + T_OFF_BAR + st * 16;
            uint32_t emptyb = fullb + 8;
            MBARRIER_WAIT_PARITY(fullb, (kt >> 2) & 1);
            uint32_t base = sb + T_OFF_ST + st * STG_B;
            uint64_t a0 = MAKE_SMEM_DESC(base);
            uint64_t a1 = MAKE_SMEM_DESC(base + 16384);
            uint64_t bd = MAKE_SMEM_DESC(base + 32768);
            #pragma unroll
            for (int sub = 0; sub < 4; sub++) {
                bool en = (kt > 0) || (sub > 0);
                mma_f16_cg1(tmem,       a0 + sub * 2, bd + sub * 2, idesc, en);
                mma_f16_cg1(tmem + 128, a1 + sub * 2, bd + sub * 2, idesc, en);
            }
            TCGEN05_COMMIT(emptyb);
        }
        TCGEN05_COMMIT(sb + T_OFF_DONE);
    }

    MBARRIER_WAIT_PARITY(sb + T_OFF_DONE, 0);
    TCGEN05_FENCE_AFTER();

    #pragma unroll
    for (int half = 0; half < 2; half++) {
        int mrow = my * 256 + half * 128 + wid * 32 + lid;
        #pragma unroll
        for (int c0 = 0; c0 < 128; c0 += 32) {
            uint32_t r[32];
            TCGEN05_LD_X32(r, tmem + half * 128 + c0);
            TCGEN05_WAIT_LD();
            if (mode == 0) {
                int* Crow = C + (size_t)mrow * D_DIM + nt * 128;
                #pragma unroll
                for (int j = 0; j < 32; j += 4) {
                    int4 v = make_int4(__float2int_rn(__uint_as_float(r[j])),
                                       __float2int_rn(__uint_as_float(r[j + 1])),
                                       __float2int_rn(__uint_as_float(r[j + 2])),
                                       __float2int_rn(__uint_as_float(r[j + 3])));
                    *(int4*)(Crow + c0 + j) = v;
                }
            } else {
                float* Orow = out + (size_t)mrow * D_DIM + nt * 128;
                #pragma unroll
                for (int j = 0; j < 32; j++) {
                    int col = nt * 128 + c0 + j;
                    Orow[c0 + j] = __fmul_rn(__uint_as_float(r[j]), __fmul_rn(0.1f, so[col]));
                }
            }
        }
    }
    __syncthreads();
    if (wid == 0) TCGEN05_DEALLOC(tmem, 256);
#endif
}

// ---------------- causal flash attention: register FA-2 + integer table softmax ----------------
#define KSTR 144      // K tile row stride (128 s8 + pad)
#define VSTR 272      // V^T tile row stride (128 half + pad)
#define ABUF 53248    // per-buffer bytes: 128*144 + 128*272
#define OFF_T2 (2 * ABUF)
#define OFF_T1 (2 * ABUF + 16384)
#define SMEM_ATT (2 * ABUF + 16384 + 128)

__global__ __launch_bounds__(256, 1) void attn_kernel() {
    extern __shared__ __align__(16) char sm[];
    float* T2s = (float*)(sm + OFF_T2);
    float* T1s = (float*)(sm + OFF_T1);
    int qt = (int)gridDim.x - 1 - (int)blockIdx.x;   // heavy tiles first
    int h = blockIdx.y;
    int tid = threadIdx.x, w = tid >> 5, ln = tid & 31;
    int qr = ln >> 2, qc = ln & 3;

    const int8_t* Kg = g_k8 + (size_t)h * S_LEN * HD;
    const char*   Vg = (const char*)(g_vh + (size_t)h * HD * S_LEN);

    // exp tables into smem
    for (int i = tid; i < 4096; i += 256) T2s[i] = g_t2[i];
    if (tid < 32) T1s[tid] = g_t1[tid];

    // Q a-fragments (resident whole kernel)
    uint32_t qa[4][4];
    {
        const int8_t* Qg = g_q8 + ((size_t)h * S_LEN + qt * 128 + w * 16) * HD;
        #pragma unroll
        for (int ks = 0; ks < 4; ks++) {
            int off = qc * 4 + ks * 32;
            qa[ks][0] = *(const uint32_t*)(Qg + qr * HD + off);
            qa[ks][1] = *(const uint32_t*)(Qg + (qr + 8) * HD + off);
            qa[ks][2] = *(const uint32_t*)(Qg + qr * HD + off + 16);
            qa[ks][3] = *(const uint32_t*)(Qg + (qr + 8) * HD + off + 16);
        }
    }

    float of[16][4];
    #pragma unroll
    for (int i = 0; i < 16; i++) { of[i][0] = of[i][1] = of[i][2] = of[i][3] = 0.0f; }
    int m0i = -(1 << 30), m1i = -(1 << 30);
    float l0 = 0.0f, l1 = 0.0f;

    // prefetch kt = 0 into buffer 0
    {
        char* Ks = sm; char* Vt = sm + 128 * KSTR;
        for (int c = tid; c < 1024; c += 256)
            cp_async16(Ks + (c >> 3) * KSTR + (c & 7) * 16, Kg + (size_t)(c >> 3) * HD + (c & 7) * 16);
        for (int c = tid; c < 2048; c += 256)
            cp_async16(Vt + (c >> 4) * VSTR + (c & 15) * 16, Vg + ((size_t)(c >> 4) * S_LEN) * 2 + (c & 15) * 16);
        cp_commit();
    }

    for (int kt = 0; kt <= qt; kt++) {
        int buf = kt & 1;
        char* Ks = sm + buf * ABUF;
        char* Vt = Ks + 128 * KSTR;
        if (kt < qt) {
            char* Ks2 = sm + (buf ^ 1) * ABUF;
            char* Vt2 = Ks2 + 128 * KSTR;
            const int8_t* Kt = Kg + (size_t)(kt + 1) * 128 * HD;
            const char*   Vs = Vg + (size_t)(kt + 1) * 128 * 2;
            for (int c = tid; c < 1024; c += 256)
                cp_async16(Ks2 + (c >> 3) * KSTR + (c & 7) * 16, Kt + (size_t)(c >> 3) * HD + (c & 7) * 16);
            for (int c = tid; c < 2048; c += 256)
                cp_async16(Vt2 + (c >> 4) * VSTR + (c & 15) * 16, Vs + ((size_t)(c >> 4) * S_LEN) * 2 + (c & 15) * 16);
            cp_commit();
            asm volatile("cp.async.wait_group 1;\n");
        } else {
            asm volatile("cp.async.wait_group 0;\n");
        }
        __syncthreads();

        // ---- S = Q K^T (exact int), per-nf to limit register pressure ----
        int ds[16][4];
        #pragma unroll
        for (int nf = 0; nf < 16; nf++) {
            int c4[4] = {0, 0, 0, 0};
            #pragma unroll
            for (int ks = 0; ks < 4; ks++) {
                const char* bp = Ks + (nf * 8 + qr) * KSTR + qc * 4 + ks * 32;
                imma16832(c4, qa[ks], *(const uint32_t*)bp, *(const uint32_t*)(bp + 16));
            }
            ds[nf][0] = c4[0]; ds[nf][1] = c4[1]; ds[nf][2] = c4[2]; ds[nf][3] = c4[3];
        }

        // causal mask on diagonal tile (score -> very negative int => p = 0)
        if (kt == qt) {
            #pragma unroll
            for (int nf = 0; nf < 16; nf++) {
                #pragma unroll
                for (int c = 0; c < 4; c++) {
                    int col = nf * 8 + qc * 2 + (c & 1);
                    int rowl = w * 16 + qr + ((c >> 1) << 3);
                    if (col > rowl) ds[nf][c] = -(1 << 29);
                }
            }
        }

        // ---- online softmax via integer table exp ----
        int tmx0 = -(1 << 30), tmx1 = -(1 << 30);
        #pragma unroll
        for (int nf = 0; nf < 16; nf++) {
            tmx0 = max(tmx0, max(ds[nf][0], ds[nf][1]));
            tmx1 = max(tmx1, max(ds[nf][2], ds[nf][3]));
        }
        tmx0 = max(tmx0, __shfl_xor_sync(0xffffffffu, tmx0, 1));
        tmx0 = max(tmx0, __shfl_xor_sync(0xffffffffu, tmx0, 2));
        tmx1 = max(tmx1, __shfl_xor_sync(0xffffffffu, tmx1, 1));
        tmx1 = max(tmx1, __shfl_xor_sync(0xffffffffu, tmx1, 2));
        int mn0 = max(m0i, tmx0), mn1 = max(m1i, tmx1);
        int da0 = mn0 - m0i, da1 = mn1 - m1i;
        float al0 = T1s[min(da0 >> 12, 31)] * T2s[da0 & 4095];
        float al1 = T1s[min(da1 >> 12, 31)] * T2s[da1 & 4095];
        m0i = mn0; m1i = mn1;
        float ps0 = 0.0f, ps1 = 0.0f;
        #pragma unroll
        for (int nf = 0; nf < 16; nf++) {
            int d0 = mn0 - ds[nf][0], d1 = mn0 - ds[nf][1];
            int d2 = mn1 - ds[nf][2], d3 = mn1 - ds[nf][3];
            float p0 = T1s[min(d0 >> 12, 31)] * T2s[d0 & 4095];
            float p1 = T1s[min(d1 >> 12, 31)] * T2s[d1 & 4095];
            float p2 = T1s[min(d2 >> 12, 31)] * T2s[d2 & 4095];
            float p3 = T1s[min(d3 >> 12, 31)] * T2s[d3 & 4095];
            ds[nf][0] = __float_as_int(p0); ds[nf][1] = __float_as_int(p1);
            ds[nf][2] = __float_as_int(p2); ds[nf][3] = __float_as_int(p3);
            ps0 += p0 + p1; ps1 += p2 + p3;
        }
        ps0 += __shfl_xor_sync(0xffffffffu, ps0, 1);
        ps0 += __shfl_xor_sync(0xffffffffu, ps0, 2);
        ps1 += __shfl_xor_sync(0xffffffffu, ps1, 1);
        ps1 += __shfl_xor_sync(0xffffffffu, ps1, 2);
        l0 = l0 * al0 + ps0;
        l1 = l1 * al1 + ps1;
        #pragma unroll
        for (int nf = 0; nf < 16; nf++) {
            of[nf][0] *= al0; of[nf][1] *= al0; of[nf][2] *= al1; of[nf][3] *= al1;
        }

        // ---- O += (Phi + Plo) * V (split fp16) ----
        #pragma unroll
        for (int ks = 0; ks < 8; ks++) {
            uint32_t ah[4], alr[4];
            splitpk(__int_as_float(ds[2 * ks][0]),     __int_as_float(ds[2 * ks][1]),     ah[0], alr[0]);
            splitpk(__int_as_float(ds[2 * ks][2]),     __int_as_float(ds[2 * ks][3]),     ah[1], alr[1]);
            splitpk(__int_as_float(ds[2 * ks + 1][0]), __int_as_float(ds[2 * ks + 1][1]), ah[2], alr[2]);
            splitpk(__int_as_float(ds[2 * ks + 1][2]), __int_as_float(ds[2 * ks + 1][3]), ah[3], alr[3]);
            #pragma unroll
            for (int nf = 0; nf < 16; nf++) {
                const char* vp = Vt + (nf * 8 + qr) * VSTR + qc * 4 + ks * 32;
                uint32_t b0 = *(const uint32_t*)vp;
                uint32_t b1 = *(const uint32_t*)(vp + 16);
                hmma16816(of[nf], ah,  b0, b1);
                hmma16816(of[nf], alr, b0, b1);
            }
        }
        __syncthreads();
    }

    // ---- epilogue: quantize round(x/0.1) clamp -127..127, write for o-proj ----
    {
        int s0 = qt * 128 + w * 16 + qr;
        int s1 = s0 + 8;
        #pragma unroll
        for (int nf = 0; nf < 16; nf++) {
            int colb = nf * 8 + qc * 2;
            float x00 = __fmul_rn(__fdiv_rn(of[nf][0], l0), 0.1f);
            float x01 = __fmul_rn(__fdiv_rn(of[nf][1], l0), 0.1f);
            float x10 = __fmul_rn(__fdiv_rn(of[nf][2], l1), 0.1f);
            float x11 = __fmul_rn(__fdiv_rn(of[nf][3], l1), 0.1f);
            int q00 = clampi(__float2int_rn(__fdiv_rn(x00, 0.1f)), -127, 127);
            int q01 = clampi(__float2int_rn(__fdiv_rn(x01, 0.1f)), -127, 127);
            int q10 = clampi(__float2int_rn(__fdiv_rn(x10, 0.1f)), -127, 127);
            int q11 = clampi(__float2int_rn(__fdiv_rn(x11, 0.1f)), -127, 127);
#if USE_TC
            int kcol = h * HD + colb;
            int ktile = kcol >> 6, cc = kcol & 63;
            uint32_t p0 = (uint32_t)__bfloat16_as_ushort(__float2bfloat16_rn((float)q00)) |
                          ((uint32_t)__bfloat16_as_ushort(__float2bfloat16_rn((float)q01)) << 16);
            uint32_t p1 = (uint32_t)__bfloat16_as_ushort(__float2bfloat16_rn((float)q10)) |
                          ((uint32_t)__bfloat16_as_ushort(__float2bfloat16_rn((float)q11)) << 16);
            *(uint32_t*)((char*)g_oa + (((size_t)((s0 >> 7) * 64 + ktile)) << 14) + sw_off(s0 & 127, cc)) = p0;
            *(uint32_t*)((char*)g_oa + (((size_t)((s1 >> 7) * 64 + ktile)) << 14) + sw_off(s1 & 127, cc)) = p1;
#else
            uint16_t u0 = (uint16_t)((uint8_t)(int8_t)q00 | ((uint16_t)(uint8_t)(int8_t)q01 << 8));
            uint16_t u1 = (uint16_t)((uint8_t)(int8_t)q10 | ((uint16_t)(uint8_t)(int8_t)q11 << 8));
            *(uint16_t*)(g_oq + (size_t)s0 * D_DIM + h * HD + colb) = u0;
            *(uint16_t*)(g_oq + (size_t)s1 * D_DIM + h * HD + colb) = u1;
#endif
        }
    }
}

// ---------------- launch ----------------
extern "C" void kernel_launch(void* const* d_in, const int* in_sizes, int n_in,
                              void* d_out, int out_size) {
    const float* hs = (const float*)d_in[0];
    const float* wq = (const float*)d_in[1];
    const float* wk = (const float*)d_in[2];
    const float* wv = (const float*)d_in[3];
    const float* wo = (const float*)d_in[4];
    const float* sq = (const float*)d_in[5];
    const float* sk = (const float*)d_in[6];
    const float* sv = (const float*)d_in[7];
    const float* so = (const float*)d_in[8];
    const int*   pos = (const int*)d_in[10];
    float* out = (float*)d_out;

    cudaFuncSetAttribute(attn_kernel, cudaFuncAttributeMaxDynamicSharedMemorySize, SMEM_ATT);
    cudaFuncSetAttribute(gemm_tc_kernel, cudaFuncAttributeMaxDynamicSharedMemorySize, SMEM_TC);

    quant_x_kernel<<<(S_LEN * D_DIM + 255) / 256, 256>>>(hs);
    convert_w_kernel<<<dim3((D_DIM * D_DIM + 255) / 256, 4), 256>>>(wq, wk, wv, wo);
    rope_table_kernel<<<(S_LEN * 64 + 255) / 256, 256>>>(pos);

    // QKV projections — exactly one of these two has a body per compiled arch
    gemm_s8_kernel<<<dim3(D_DIM / GBN, S_LEN / GBM, 3), 128>>>(0);
    gemm_tc_kernel<<<dim3(D_DIM / 128, S_LEN / 256, 3), 128, SMEM_TC>>>(0, so, out);

    ropequant_kernel<<<(S_LEN * D_DIM + 255) / 256, 256>>>(sq, sk, sv);

    attn_kernel<<<dim3(S_LEN / 128, H_NUM), 256, SMEM_ATT>>>();

    // o-proj (tc path fuses the output scaling; wmma path uses final_kernel)
    gemm_s8_kernel<<<dim3(D_DIM / GBN, S_LEN / GBM, 1), 128>>>(1);
    gemm_tc_kernel<<<dim3(D_DIM / 128, S_LEN / 256, 1), 128, SMEM_TC>>>(1, so, out);

    final_kernel<<<(S_LEN * D_DIM + 255) / 256, 256>>>(so, out);
}

// round 8
// speedup vs baseline: 1.4430x; 1.2478x over previous
#include <cuda_runtime.h>
#include <cuda_fp16.h>
#include <cuda_bf16.h>
#include <math.h>
#include <stdint.h>

#define S_LEN 2048
#define D_DIM 4096
#define H_NUM 32
#define HD    128
#define KDIM  4096

// Arch-specific feature gate: tcgen05 only exists under 'a'/'f' targets.
#if defined(__CUDA_ARCH__) && (defined(__CUDA_ARCH_FEAT_SM103_ALL) || defined(__CUDA_ARCH_FEAT_SM100_ALL) || defined(__CUDA_ARCH_SPECIFIC__) || defined(__CUDA_ARCH_FAMILY_SPECIFIC__))
#define USE_TC 1
#else
#define USE_TC 0
#endif

// ---------------- static scratch (allocation-free rule) ----------------
__device__ __nv_bfloat16 g_xa[S_LEN * D_DIM];       // quantized hidden, bf16 SW128-tiled
__device__ __nv_bfloat16 g_wb[4][D_DIM * D_DIM];    // weights bf16 SW128-tiled
__device__ __nv_bfloat16 g_oa[S_LEN * D_DIM];       // attn out bf16 SW128-tiled
__device__ int    g_pint[3][S_LEN * D_DIM];         // raw int32 q/k/v projections
__device__ int8_t g_q8[H_NUM * S_LEN * HD];         // roped+quantized Q  [H,S,HD]
__device__ int8_t g_k8[H_NUM * S_LEN * HD];         // roped+quantized K  [H,S,HD]
__device__ __half g_vh[H_NUM * HD * S_LEN];         // quantized V TRANSPOSED [H,HD,S]
__device__ float2 g_rope[S_LEN * 64];               // (cos,sin) table
__device__ float  g_t2[4096];                       // exp(-lo*SC)
__device__ float  g_t1[32];                         // exp(-hi*4096*SC)

// ---------------- helpers ----------------
__device__ __forceinline__ void cp_async16(void* smem, const void* gmem) {
    unsigned saddr = (unsigned)__cvta_generic_to_shared(smem);
    asm volatile("cp.async.cg.shared.global [%0], [%1], 16;\n" :: "r"(saddr), "l"(gmem));
}
__device__ __forceinline__ void cp_commit() { asm volatile("cp.async.commit_group;\n"); }
__device__ __forceinline__ int clampi(int v, int lo, int hi) { return max(lo, min(hi, v)); }

// swizzled byte offset inside a [rows x 128B] SW128 tile for (row r, bf16 col c<64)
__device__ __forceinline__ uint32_t sw_off(int r, int c) {
    return (uint32_t)((r * 128 + c * 2) ^ ((r & 7) << 4));
}

// mma.sync wrappers (legal on base arch; used by attention)
__device__ __forceinline__ void imma16832(int* c, const uint32_t* a, uint32_t b0, uint32_t b1) {
    asm volatile("mma.sync.aligned.m16n8k32.row.col.s32.s8.s8.s32 "
        "{%0,%1,%2,%3}, {%4,%5,%6,%7}, {%8,%9}, {%0,%1,%2,%3};"
        : "+r"(c[0]), "+r"(c[1]), "+r"(c[2]), "+r"(c[3])
        : "r"(a[0]), "r"(a[1]), "r"(a[2]), "r"(a[3]), "r"(b0), "r"(b1));
}
__device__ __forceinline__ void hmma16816(float* c, const uint32_t* a, uint32_t b0, uint32_t b1) {
    asm volatile("mma.sync.aligned.m16n8k16.row.col.f32.f16.f16.f32 "
        "{%0,%1,%2,%3}, {%4,%5,%6,%7}, {%8,%9}, {%0,%1,%2,%3};"
        : "+f"(c[0]), "+f"(c[1]), "+f"(c[2]), "+f"(c[3])
        : "r"(a[0]), "r"(a[1]), "r"(a[2]), "r"(a[3]), "r"(b0), "r"(b1));
}
__device__ __forceinline__ void splitpk(float x0, float x1, uint32_t& hi, uint32_t& lo) {
    __half h0 = __float2half_rn(x0), h1 = __float2half_rn(x1);
    __half e0 = __float2half_rn(x0 - __half2float(h0));
    __half e1 = __float2half_rn(x1 - __half2float(h1));
    hi = (uint32_t)__half_as_ushort(h0) | ((uint32_t)__half_as_ushort(h1) << 16);
    lo = (uint32_t)__half_as_ushort(e0) | ((uint32_t)__half_as_ushort(e1) << 16);
}
__device__ __forceinline__ uint32_t bfpack(int a, int b) {
    return (uint32_t)__bfloat16_as_ushort(__float2bfloat16_rn((float)a)) |
           ((uint32_t)__bfloat16_as_ushort(__float2bfloat16_rn((float)b)) << 16);
}

#if USE_TC
__device__ __forceinline__ uint32_t smem_u32(const void* p) {
    uint32_t a;
    asm("{ .reg .u64 t; cvta.to.shared.u64 t, %1; cvt.u32.u64 %0, t; }" : "=r"(a) : "l"(p));
    return a;
}
#define MBARRIER_INIT(addr, cnt) \
    asm volatile("mbarrier.init.shared.b64 [%0], %1;" :: "r"((uint32_t)(addr)), "r"((uint32_t)(cnt)) : "memory")
#define MBARRIER_EXPECT_TX(addr, bytes) \
    asm volatile("mbarrier.arrive.expect_tx.shared.b64 _, [%0], %1;" :: "r"((uint32_t)(addr)), "r"((uint32_t)(bytes)) : "memory")
#define MBARRIER_WAIT_PARITY(addr, ph) do {                                   \
    uint32_t _m = (uint32_t)(addr); uint32_t _p = (uint32_t)(ph);             \
    asm volatile("{\n\t.reg .pred P1;\n\t"                                    \
        "WL_%=:\n\t"                                                          \
        "mbarrier.try_wait.parity.acquire.cta.shared::cta.b64 P1, [%0], %1, 0x989680;\n\t" \
        "@P1 bra.uni WD_%=;\n\t"                                              \
        "bra.uni WL_%=;\n\t"                                                  \
        "WD_%=:\n\t}"                                                         \
        :: "r"(_m), "r"(_p) : "memory");                                      \
} while (0)
#define TCGEN05_ALLOC(sma, n) \
    asm volatile("tcgen05.alloc.cta_group::1.sync.aligned.shared::cta.b32 [%0], %1;" \
        :: "r"((uint32_t)(sma)), "r"((uint32_t)(n)) : "memory")
#define TCGEN05_DEALLOC(tm, n) \
    asm volatile("tcgen05.dealloc.cta_group::1.sync.aligned.b32 %0, %1;" :: "r"(tm), "r"((uint32_t)(n)))
#define TCGEN05_RELINQ() \
    asm volatile("tcgen05.relinquish_alloc_permit.cta_group::1.sync.aligned;")
#define TCGEN05_COMMIT(mb) \
    asm volatile("tcgen05.commit.cta_group::1.mbarrier::arrive::one.shared::cluster.b64 [%0];" \
        :: "r"((uint32_t)(mb)) : "memory")
#define TCGEN05_FENCE_AFTER() asm volatile("tcgen05.fence::after_thread_sync;" ::: "memory")
#define TCGEN05_WAIT_LD()     asm volatile("tcgen05.wait::ld.sync.aligned;" ::: "memory")
#define TCGEN05_LD_X32(r, tma) \
    asm volatile("tcgen05.ld.sync.aligned.32x32b.x32.b32 " \
        "{%0,%1,%2,%3,%4,%5,%6,%7,%8,%9,%10,%11,%12,%13,%14,%15," \
        "%16,%17,%18,%19,%20,%21,%22,%23,%24,%25,%26,%27,%28,%29,%30,%31}, [%32];" \
        : "=r"((r)[0]), "=r"((r)[1]), "=r"((r)[2]), "=r"((r)[3]),   \
          "=r"((r)[4]), "=r"((r)[5]), "=r"((r)[6]), "=r"((r)[7]),   \
          "=r"((r)[8]), "=r"((r)[9]), "=r"((r)[10]), "=r"((r)[11]), \
          "=r"((r)[12]), "=r"((r)[13]), "=r"((r)[14]), "=r"((r)[15]), \
          "=r"((r)[16]), "=r"((r)[17]), "=r"((r)[18]), "=r"((r)[19]), \
          "=r"((r)[20]), "=r"((r)[21]), "=r"((r)[22]), "=r"((r)[23]), \
          "=r"((r)[24]), "=r"((r)[25]), "=r"((r)[26]), "=r"((r)[27]), \
          "=r"((r)[28]), "=r"((r)[29]), "=r"((r)[30]), "=r"((r)[31]) \
        : "r"(tma))
static constexpr uint64_t SMEM_DESC_BASE_SW128 =
    (uint64_t(2) << 61) | (uint64_t(1) << 46) | (uint64_t(64) << 32) | (uint64_t(1) << 16);
#define MAKE_SMEM_DESC(ba) (SMEM_DESC_BASE_SW128 | ((uint64_t)((ba) >> 4) & 0x3FFF))
__device__ __forceinline__ void bulk_g2s(uint32_t dst, const void* src, uint32_t bytes, uint32_t mbar) {
    asm volatile("cp.async.bulk.shared::cluster.global.mbarrier::complete_tx::bytes [%0], [%1], %2, [%3];"
        :: "r"(dst), "l"(src), "r"(bytes), "r"(mbar) : "memory");
}
__device__ __forceinline__ void mma_f16_cg1(uint32_t d, uint64_t ad, uint64_t bd, uint32_t idesc, bool en) {
    uint32_t e = en ? 1u : 0u;
    asm volatile("{\n\t.reg .pred p;\n\tsetp.ne.u32 p, %5, 0;\n\t"
        "tcgen05.mma.cta_group::1.kind::f16 [%0], %1, %2, %3, {%4, %4, %4, %4}, p;\n\t}"
        :: "r"(d), "l"(ad), "l"(bd), "r"(idesc), "r"(0u), "r"(e) : "memory");
}
#endif  // USE_TC

// ---------------- elementwise kernels (vectorized swizzled stores) ----------------
__global__ void quant_x_kernel(const float* __restrict__ hs) {
    int t = blockIdx.x * blockDim.x + threadIdx.x;
    if (t >= S_LEN * D_DIM / 8) return;
    int idx = t * 8;
    int s = idx >> 12, d = idx & (D_DIM - 1);
    float4 v0 = *(const float4*)(hs + idx);
    float4 v1 = *(const float4*)(hs + idx + 4);
    int q0 = clampi(__float2int_rn(__fdiv_rn(v0.x, 0.1f)), -128, 127);
    int q1 = clampi(__float2int_rn(__fdiv_rn(v0.y, 0.1f)), -128, 127);
    int q2 = clampi(__float2int_rn(__fdiv_rn(v0.z, 0.1f)), -128, 127);
    int q3 = clampi(__float2int_rn(__fdiv_rn(v0.w, 0.1f)), -128, 127);
    int q4 = clampi(__float2int_rn(__fdiv_rn(v1.x, 0.1f)), -128, 127);
    int q5 = clampi(__float2int_rn(__fdiv_rn(v1.y, 0.1f)), -128, 127);
    int q6 = clampi(__float2int_rn(__fdiv_rn(v1.z, 0.1f)), -128, 127);
    int q7 = clampi(__float2int_rn(__fdiv_rn(v1.w, 0.1f)), -128, 127);
    int mt = s >> 7, r = s & 127, kt = d >> 6, c = d & 63;
    *(uint4*)((char*)g_xa + (((size_t)(mt * 64 + kt)) << 14) + sw_off(r, c)) =
        make_uint4(bfpack(q0, q1), bfpack(q2, q3), bfpack(q4, q5), bfpack(q6, q7));
}

__global__ void convert_w_kernel(const float* __restrict__ wq, const float* __restrict__ wk,
                                 const float* __restrict__ wv, const float* __restrict__ wo) {
    int t = blockIdx.x * blockDim.x + threadIdx.x;
    int z = blockIdx.y;
    if (t >= D_DIM * D_DIM / 8) return;
    const float* src = (z == 0) ? wq : (z == 1) ? wk : (z == 2) ? wv : wo;
    int idx = t * 8;
    int o = idx >> 12, k = idx & (D_DIM - 1);
    float4 v0 = *(const float4*)(src + idx);
    float4 v1 = *(const float4*)(src + idx + 4);
    int q0 = __float2int_rn(v0.x), q1 = __float2int_rn(v0.y);
    int q2 = __float2int_rn(v0.z), q3 = __float2int_rn(v0.w);
    int q4 = __float2int_rn(v1.x), q5 = __float2int_rn(v1.y);
    int q6 = __float2int_rn(v1.z), q7 = __float2int_rn(v1.w);
    int nt = o >> 7, r = o & 127, kt = k >> 6, c = k & 63;
    *(uint4*)((char*)g_wb[z] + (((size_t)(nt * 64 + kt)) << 14) + sw_off(r, c)) =
        make_uint4(bfpack(q0, q1), bfpack(q2, q3), bfpack(q4, q5), bfpack(q6, q7));
}

__global__ void rope_table_kernel(const int* __restrict__ pos) {
    int idx = blockIdx.x * blockDim.x + threadIdx.x;
    const double SCd = (double)0.1f * (double)0.1f / 11.313708498984760390;
    if (idx < 4096) g_t2[idx] = (float)exp(-SCd * (double)idx);
    if (idx < 32)   g_t1[idx] = (float)exp(-SCd * 4096.0 * (double)idx);
    if (idx >= S_LEN * 64) return;
    int s = idx >> 6, i = idx & 63;
    float e = (float)(2 * i) * (1.0f / 128.0f);
    float powf32 = (float)pow(10000.0, (double)e);
    float invf = 1.0f / powf32;
    float ang = (float)pos[s] * invf;
    double a = (double)ang;
    g_rope[idx] = make_float2((float)cos(a), (float)sin(a));
}

// Q/K rope + requant (coalesced reads and 1B-contiguous writes)
__global__ void ropequant_qk_kernel(const float* __restrict__ sq, const float* __restrict__ sk) {
    int idx = blockIdx.x * blockDim.x + threadIdx.x;
    if (idx >= S_LEN * D_DIM) return;
    int s = idx >> 12, o = idx & (D_DIM - 1);
    int h = o >> 7, j = o & 127;
    float2 cs = g_rope[(s << 6) + (j & 63)];
    int o2 = (h << 7) + ((j < 64) ? (j + 64) : (j - 64));
    float sign = (j < 64) ? -1.0f : 1.0f;
    int base = s * D_DIM;
    int dsti = (h * S_LEN + s) * HD + j;
    {
        float a = __fmul_rn((float)g_pint[0][base + o],  __fmul_rn(0.1f, sq[o]));
        float b = __fmul_rn((float)g_pint[0][base + o2], __fmul_rn(0.1f, sq[o2])) * sign;
        float r = __fadd_rn(__fmul_rn(a, cs.x), __fmul_rn(b, cs.y));
        g_q8[dsti] = (int8_t)clampi(__float2int_rn(__fdiv_rn(r, 0.1f)), -128, 127);
    }
    {
        float a = __fmul_rn((float)g_pint[1][base + o],  __fmul_rn(0.1f, sk[o]));
        float b = __fmul_rn((float)g_pint[1][base + o2], __fmul_rn(0.1f, sk[o2])) * sign;
        float r = __fadd_rn(__fmul_rn(a, cs.x), __fmul_rn(b, cs.y));
        g_k8[dsti] = (int8_t)clampi(__float2int_rn(__fdiv_rn(r, 0.1f)), -128, 127);
    }
}

// V quantize + transpose through smem: coalesced reads AND writes
__global__ void transpose_v_kernel(const float* __restrict__ sv) {
    __shared__ __half ts[32][136];
    int h = blockIdx.z, j0 = blockIdx.y * 32, s0 = blockIdx.x * 128;
    int tid = threadIdx.x;
    int tx = tid & 31, ty = tid >> 5;   // 8 rows of 32
    int j = j0 + tx;
    float sc = __fmul_rn(0.1f, sv[h * 128 + j]);
    #pragma unroll
    for (int si = ty; si < 128; si += 8) {
        int s = s0 + si;
        float a = __fmul_rn((float)g_pint[2][s * D_DIM + h * 128 + j], sc);
        int q = clampi(__float2int_rn(__fdiv_rn(a, 0.1f)), -128, 127);
        ts[tx][si] = __float2half_rn((float)q);
    }
    __syncthreads();
    #pragma unroll
    for (int e = tid; e < 32 * 128; e += 256) {
        int jj = e >> 7, s = e & 127;
        g_vh[((size_t)h * HD + j0 + jj) * S_LEN + s0 + s] = ts[jj][s];
    }
}

// ---------------- tcgen05 bf16 GEMM (M=256 via 2x M128, N=128, K-stage 64) ----------------
#define NST 4
#define STG_B 49152                 // A0 16KB + A1 16KB + B 16KB
#define T_OFF_TM 0
#define T_OFF_BAR 16
#define T_OFF_DONE 80
#define T_OFF_ST 1024
#define SMEM_TC (T_OFF_ST + NST * STG_B)   // 197632

__global__ __launch_bounds__(128, 1) __cluster_dims__(1, 1, 1)
void gemm_tc_kernel(int mode, const float* __restrict__ so, float* __restrict__ out) {
#if USE_TC
    extern __shared__ __align__(1024) char sm[];
    uint32_t sb = smem_u32(sm);
    int tid = threadIdx.x, wid = tid >> 5, lid = tid & 31;

    const char* A; const char* B; int* C;
    if (mode == 0) { A = (const char*)g_xa; B = (const char*)g_wb[blockIdx.z]; C = g_pint[blockIdx.z]; }
    else           { A = (const char*)g_oa; B = (const char*)g_wb[3];          C = g_pint[0]; }
    int my = blockIdx.y, nt = blockIdx.x;

    if (wid == 0) { TCGEN05_ALLOC(sb + T_OFF_TM, 256); TCGEN05_RELINQ(); }
    if (tid == 0) {
        #pragma unroll
        for (int s = 0; s < NST; s++) {
            MBARRIER_INIT(sb + T_OFF_BAR + s * 16, 1);
            MBARRIER_INIT(sb + T_OFF_BAR + s * 16 + 8, 1);
        }
        MBARRIER_INIT(sb + T_OFF_DONE, 1);
    }
    __syncthreads();
    uint32_t tmem;
    asm volatile("ld.shared.b32 %0, [%1];" : "=r"(tmem) : "r"(sb + T_OFF_TM));

    const int KT = KDIM / 64;

    if (tid == 0) {
        for (int kt = 0; kt < KT; kt++) {
            int st = kt & (NST - 1);
            uint32_t fullb = sb + T_OFF_BAR + st * 16;
            uint32_t emptyb = fullb + 8;
            if (kt >= NST) MBARRIER_WAIT_PARITY(emptyb, ((kt >> 2) - 1) & 1);
            MBARRIER_EXPECT_TX(fullb, STG_B);
            uint32_t dst = sb + T_OFF_ST + st * STG_B;
            bulk_g2s(dst,         A + ((size_t)((2 * my)     * 64 + kt) << 14), 16384, fullb);
            bulk_g2s(dst + 16384, A + ((size_t)((2 * my + 1) * 64 + kt) << 14), 16384, fullb);
            bulk_g2s(dst + 32768, B + ((size_t)(nt * 64 + kt) << 14),           16384, fullb);
        }
    } else if (tid == 32) {
        const uint32_t idesc = (1u << 4) | (1u << 7) | (1u << 10) | (16u << 17) | (8u << 24);
        for (int kt = 0; kt < KT; kt++) {
            int st = kt & (NST - 1);
            uint32_t fullb = sb + T_OFF_BAR + st * 16;
            uint32_t emptyb = fullb + 8;
            MBARRIER_WAIT_PARITY(fullb, (kt >> 2) & 1);
            uint32_t base = sb + T_OFF_ST + st * STG_B;
            uint64_t a0 = MAKE_SMEM_DESC(base);
            uint64_t a1 = MAKE_SMEM_DESC(base + 16384);
            uint64_t bd = MAKE_SMEM_DESC(base + 32768);
            #pragma unroll
            for (int sub = 0; sub < 4; sub++) {
                bool en = (kt > 0) || (sub > 0);
                mma_f16_cg1(tmem,       a0 + sub * 2, bd + sub * 2, idesc, en);
                mma_f16_cg1(tmem + 128, a1 + sub * 2, bd + sub * 2, idesc, en);
            }
            TCGEN05_COMMIT(emptyb);
        }
        TCGEN05_COMMIT(sb + T_OFF_DONE);
    }

    MBARRIER_WAIT_PARITY(sb + T_OFF_DONE, 0);
    TCGEN05_FENCE_AFTER();

    #pragma unroll
    for (int half = 0; half < 2; half++) {
        int mrow = my * 256 + half * 128 + wid * 32 + lid;
        #pragma unroll
        for (int c0 = 0; c0 < 128; c0 += 32) {
            uint32_t r[32];
            TCGEN05_LD_X32(r, tmem + half * 128 + c0);
            TCGEN05_WAIT_LD();
            if (mode == 0) {
                int* Crow = C + (size_t)mrow * D_DIM + nt * 128;
                #pragma unroll
                for (int j = 0; j < 32; j += 4) {
                    int4 v = make_int4(__float2int_rn(__uint_as_float(r[j])),
                                       __float2int_rn(__uint_as_float(r[j + 1])),
                                       __float2int_rn(__uint_as_float(r[j + 2])),
                                       __float2int_rn(__uint_as_float(r[j + 3])));
                    *(int4*)(Crow + c0 + j) = v;
                }
            } else {
                float* Orow = out + (size_t)mrow * D_DIM + nt * 128;
                #pragma unroll
                for (int j = 0; j < 32; j++) {
                    int col = nt * 128 + c0 + j;
                    Orow[c0 + j] = __fmul_rn(__uint_as_float(r[j]), __fmul_rn(0.1f, so[col]));
                }
            }
        }
    }
    __syncthreads();
    if (wid == 0) TCGEN05_DEALLOC(tmem, 256);
#endif
}

// ---------------- causal flash attention: register FA-2 + integer table softmax ----------------
#define KSTR 144
#define VSTR 272
#define ABUF 53248
#define OFF_T2 (2 * ABUF)
#define OFF_T1 (2 * ABUF + 16384)
#define SMEM_ATT (2 * ABUF + 16384 + 128)

__global__ __launch_bounds__(256, 1) void attn_kernel() {
    extern __shared__ __align__(16) char sm[];
    float* T2s = (float*)(sm + OFF_T2);
    float* T1s = (float*)(sm + OFF_T1);
    int qt = (int)gridDim.x - 1 - (int)blockIdx.x;
    int h = blockIdx.y;
    int tid = threadIdx.x, w = tid >> 5, ln = tid & 31;
    int qr = ln >> 2, qc = ln & 3;

    const int8_t* Kg = g_k8 + (size_t)h * S_LEN * HD;
    const char*   Vg = (const char*)(g_vh + (size_t)h * HD * S_LEN);

    for (int i = tid; i < 4096; i += 256) T2s[i] = g_t2[i];
    if (tid < 32) T1s[tid] = g_t1[tid];

    uint32_t qa[4][4];
    {
        const int8_t* Qg = g_q8 + ((size_t)h * S_LEN + qt * 128 + w * 16) * HD;
        #pragma unroll
        for (int ks = 0; ks < 4; ks++) {
            int off = qc * 4 + ks * 32;
            qa[ks][0] = *(const uint32_t*)(Qg + qr * HD + off);
            qa[ks][1] = *(const uint32_t*)(Qg + (qr + 8) * HD + off);
            qa[ks][2] = *(const uint32_t*)(Qg + qr * HD + off + 16);
            qa[ks][3] = *(const uint32_t*)(Qg + (qr + 8) * HD + off + 16);
        }
    }

    float of[16][4];
    #pragma unroll
    for (int i = 0; i < 16; i++) { of[i][0] = of[i][1] = of[i][2] = of[i][3] = 0.0f; }
    int m0i = -(1 << 30), m1i = -(1 << 30);
    float l0 = 0.0f, l1 = 0.0f;

    {
        char* Ks = sm; char* Vt = sm + 128 * KSTR;
        for (int c = tid; c < 1024; c += 256)
            cp_async16(Ks + (c >> 3) * KSTR + (c & 7) * 16, Kg + (size_t)(c >> 3) * HD + (c & 7) * 16);
        for (int c = tid; c < 2048; c += 256)
            cp_async16(Vt + (c >> 4) * VSTR + (c & 15) * 16, Vg + ((size_t)(c >> 4) * S_LEN) * 2 + (c & 15) * 16);
        cp_commit();
    }

    for (int kt = 0; kt <= qt; kt++) {
        int buf = kt & 1;
        char* Ks = sm + buf * ABUF;
        char* Vt = Ks + 128 * KSTR;
        if (kt < qt) {
            char* Ks2 = sm + (buf ^ 1) * ABUF;
            char* Vt2 = Ks2 + 128 * KSTR;
            const int8_t* Kt = Kg + (size_t)(kt + 1) * 128 * HD;
            const char*   Vs = Vg + (size_t)(kt + 1) * 128 * 2;
            for (int c = tid; c < 1024; c += 256)
                cp_async16(Ks2 + (c >> 3) * KSTR + (c & 7) * 16, Kt + (size_t)(c >> 3) * HD + (c & 7) * 16);
            for (int c = tid; c < 2048; c += 256)
                cp_async16(Vt2 + (c >> 4) * VSTR + (c & 15) * 16, Vs + ((size_t)(c >> 4) * S_LEN) * 2 + (c & 15) * 16);
            cp_commit();
            asm volatile("cp.async.wait_group 1;\n");
        } else {
            asm volatile("cp.async.wait_group 0;\n");
        }
        __syncthreads();

        int ds[16][4];
        #pragma unroll
        for (int nf = 0; nf < 16; nf++) {
            int c4[4] = {0, 0, 0, 0};
            #pragma unroll
            for (int ks = 0; ks < 4; ks++) {
                const char* bp = Ks + (nf * 8 + qr) * KSTR + qc * 4 + ks * 32;
                imma16832(c4, qa[ks], *(const uint32_t*)bp, *(const uint32_t*)(bp + 16));
            }
            ds[nf][0] = c4[0]; ds[nf][1] = c4[1]; ds[nf][2] = c4[2]; ds[nf][3] = c4[3];
        }

        if (kt == qt) {
            #pragma unroll
            for (int nf = 0; nf < 16; nf++) {
                #pragma unroll
                for (int c = 0; c < 4; c++) {
                    int col = nf * 8 + qc * 2 + (c & 1);
                    int rowl = w * 16 + qr + ((c >> 1) << 3);
                    if (col > rowl) ds[nf][c] = -(1 << 29);
                }
            }
        }

        int tmx0 = -(1 << 30), tmx1 = -(1 << 30);
        #pragma unroll
        for (int nf = 0; nf < 16; nf++) {
            tmx0 = max(tmx0, max(ds[nf][0], ds[nf][1]));
            tmx1 = max(tmx1, max(ds[nf][2], ds[nf][3]));
        }
        tmx0 = max(tmx0, __shfl_xor_sync(0xffffffffu, tmx0, 1));
        tmx0 = max(tmx0, __shfl_xor_sync(0xffffffffu, tmx0, 2));
        tmx1 = max(tmx1, __shfl_xor_sync(0xffffffffu, tmx1, 1));
        tmx1 = max(tmx1, __shfl_xor_sync(0xffffffffu, tmx1, 2));
        int mn0 = max(m0i, tmx0), mn1 = max(m1i, tmx1);
        int da0 = mn0 - m0i, da1 = mn1 - m1i;
        float al0 = T1s[min(da0 >> 12, 31)] * T2s[da0 & 4095];
        float al1 = T1s[min(da1 >> 12, 31)] * T2s[da1 & 4095];
        m0i = mn0; m1i = mn1;
        float ps0 = 0.0f, ps1 = 0.0f;
        #pragma unroll
        for (int nf = 0; nf < 16; nf++) {
            int d0 = mn0 - ds[nf][0], d1 = mn0 - ds[nf][1];
            int d2 = mn1 - ds[nf][2], d3 = mn1 - ds[nf][3];
            float p0 = T1s[min(d0 >> 12, 31)] * T2s[d0 & 4095];
            float p1 = T1s[min(d1 >> 12, 31)] * T2s[d1 & 4095];
            float p2 = T1s[min(d2 >> 12, 31)] * T2s[d2 & 4095];
            float p3 = T1s[min(d3 >> 12, 31)] * T2s[d3 & 4095];
            ds[nf][0] = __float_as_int(p0); ds[nf][1] = __float_as_int(p1);
            ds[nf][2] = __float_as_int(p2); ds[nf][3] = __float_as_int(p3);
            ps0 += p0 + p1; ps1 += p2 + p3;
        }
        ps0 += __shfl_xor_sync(0xffffffffu, ps0, 1);
        ps0 += __shfl_xor_sync(0xffffffffu, ps0, 2);
        ps1 += __shfl_xor_sync(0xffffffffu, ps1, 1);
        ps1 += __shfl_xor_sync(0xffffffffu, ps1, 2);
        l0 = l0 * al0 + ps0;
        l1 = l1 * al1 + ps1;
        #pragma unroll
        for (int nf = 0; nf < 16; nf++) {
            of[nf][0] *= al0; of[nf][1] *= al0; of[nf][2] *= al1; of[nf][3] *= al1;
        }

        #pragma unroll
        for (int ks = 0; ks < 8; ks++) {
            uint32_t ah[4], alr[4];
            splitpk(__int_as_float(ds[2 * ks][0]),     __int_as_float(ds[2 * ks][1]),     ah[0], alr[0]);
            splitpk(__int_as_float(ds[2 * ks][2]),     __int_as_float(ds[2 * ks][3]),     ah[1], alr[1]);
            splitpk(__int_as_float(ds[2 * ks + 1][0]), __int_as_float(ds[2 * ks + 1][1]), ah[2], alr[2]);
            splitpk(__int_as_float(ds[2 * ks + 1][2]), __int_as_float(ds[2 * ks + 1][3]), ah[3], alr[3]);
            #pragma unroll
            for (int nf = 0; nf < 16; nf++) {
                const char* vp = Vt + (nf * 8 + qr) * VSTR + qc * 4 + ks * 32;
                uint32_t b0 = *(const uint32_t*)vp;
                uint32_t b1 = *(const uint32_t*)(vp + 16);
                hmma16816(of[nf], ah,  b0, b1);
                hmma16816(of[nf], alr, b0, b1);
            }
        }
        __syncthreads();
    }

    {
        int s0 = qt * 128 + w * 16 + qr;
        int s1 = s0 + 8;
        #pragma unroll
        for (int nf = 0; nf < 16; nf++) {
            int colb = nf * 8 + qc * 2;
            float x00 = __fmul_rn(__fdiv_rn(of[nf][0], l0), 0.1f);
            float x01 = __fmul_rn(__fdiv_rn(of[nf][1], l0), 0.1f);
            float x10 = __fmul_rn(__fdiv_rn(of[nf][2], l1), 0.1f);
            float x11 = __fmul_rn(__fdiv_rn(of[nf][3], l1), 0.1f);
            int q00 = clampi(__float2int_rn(__fdiv_rn(x00, 0.1f)), -127, 127);
            int q01 = clampi(__float2int_rn(__fdiv_rn(x01, 0.1f)), -127, 127);
            int q10 = clampi(__float2int_rn(__fdiv_rn(x10, 0.1f)), -127, 127);
            int q11 = clampi(__float2int_rn(__fdiv_rn(x11, 0.1f)), -127, 127);
            int kcol = h * HD + colb;
            int ktile = kcol >> 6, cc = kcol & 63;
            uint32_t p0 = bfpack(q00, q01);
            uint32_t p1 = bfpack(q10, q11);
            *(uint32_t*)((char*)g_oa + (((size_t)((s0 >> 7) * 64 + ktile)) << 14) + sw_off(s0 & 127, cc)) = p0;
            *(uint32_t*)((char*)g_oa + (((size_t)((s1 >> 7) * 64 + ktile)) << 14) + sw_off(s1 & 127, cc)) = p1;
        }
    }
}

// ---------------- launch ----------------
extern "C" void kernel_launch(void* const* d_in, const int* in_sizes, int n_in,
                              void* d_out, int out_size) {
    const float* hs = (const float*)d_in[0];
    const float* wq = (const float*)d_in[1];
    const float* wk = (const float*)d_in[2];
    const float* wv = (const float*)d_in[3];
    const float* wo = (const float*)d_in[4];
    const float* sq = (const float*)d_in[5];
    const float* sk = (const float*)d_in[6];
    const float* sv = (const float*)d_in[7];
    const float* so = (const float*)d_in[8];
    const int*   pos = (const int*)d_in[10];
    float* out = (float*)d_out;

    cudaFuncSetAttribute(attn_kernel, cudaFuncAttributeMaxDynamicSharedMemorySize, SMEM_ATT);
    cudaFuncSetAttribute(gemm_tc_kernel, cudaFuncAttributeMaxDynamicSharedMemorySize, SMEM_TC);

    quant_x_kernel<<<(S_LEN * D_DIM / 8 + 255) / 256, 256>>>(hs);
    convert_w_kernel<<<dim3((D_DIM * D_DIM / 8 + 255) / 256, 4), 256>>>(wq, wk, wv, wo);
    rope_table_kernel<<<(S_LEN * 64 + 255) / 256, 256>>>(pos);

    gemm_tc_kernel<<<dim3(D_DIM / 128, S_LEN / 256, 3), 128, SMEM_TC>>>(0, so, out);   // QKV

    ropequant_qk_kernel<<<(S_LEN * D_DIM + 255) / 256, 256>>>(sq, sk);
    transpose_v_kernel<<<dim3(S_LEN / 128, 4, H_NUM), 256>>>(sv);

    attn_kernel<<<dim3(S_LEN / 128, H_NUM), 256, SMEM_ATT>>>();

    gemm_tc_kernel<<<dim3(D_DIM / 128, S_LEN / 256, 1), 128, SMEM_TC>>>(1, so, out);   // o-proj
}